// round 9
// baseline (speedup 1.0000x reference)
#include <cuda_runtime.h>
#include <cstdint>

#define Bn 16
#define Tn 2048
#define Cn 1024
#define Hn 64

// ---------------- global scratch (pre-split bf16 operands) ----------------
__device__ uint32_t g_qhi[Bn * Tn * 32];   // Q scaled, bf16-pair words [t][kslot(h/2)]
__device__ uint32_t g_qlo[Bn * Tn * 32];
__device__ uint32_t g_khi[Bn * Tn * 32];   // K words [t][kslot(h/2)]
__device__ uint32_t g_klo[Bn * Tn * 32];
__device__ unsigned short g_vhiT[Bn * Hn * Tn];  // V^T bf16 [b][h][eperm(t)]
__device__ unsigned short g_vloT[Bn * Hn * Tn];
__device__ uint32_t g_whi[3 * 32 * 64 * 16];     // W words [which][kt][n][kslot(k/2)]
__device__ uint32_t g_wlo[3 * 32 * 64 * 16];

// ---------------- helpers ----------------
__device__ __forceinline__ unsigned short b16(float x) {
    unsigned short h;
    asm("cvt.rn.bf16.f32 %0, %1;" : "=h"(h) : "f"(x));
    return h;
}
__device__ __forceinline__ float fb16(unsigned short h) {
    return __uint_as_float((uint32_t)h << 16);
}
__device__ __forceinline__ uint32_t pkb(unsigned short lo, unsigned short hi) {
    uint32_t r;
    asm("mov.b32 %0, {%1, %2};" : "=r"(r) : "h"(lo), "h"(hi));
    return r;
}
// split pair (x0 = k-even, x1 = k-odd) into hi-word and lo-word
__device__ __forceinline__ void spb2(float x0, float x1, uint32_t& hw, uint32_t& lw) {
    unsigned short h0 = b16(x0), h1 = b16(x1);
    unsigned short l0 = b16(x0 - fb16(h0)), l1 = b16(x1 - fb16(h1));
    hw = pkb(h0, h1);
    lw = pkb(l0, l1);
}
// bf16 m16n8k16 mma, fp32 accum
__device__ __forceinline__ void mmab(float c[4],
                                     uint32_t a0, uint32_t a1, uint32_t a2, uint32_t a3,
                                     uint32_t b0, uint32_t b1) {
    asm volatile(
        "mma.sync.aligned.m16n8k16.row.col.f32.bf16.bf16.f32 "
        "{%0,%1,%2,%3}, {%4,%5,%6,%7}, {%8,%9}, {%0,%1,%2,%3};"
        : "+f"(c[0]), "+f"(c[1]), "+f"(c[2]), "+f"(c[3])
        : "r"(a0), "r"(a1), "r"(a2), "r"(a3), "r"(b0), "r"(b1));
}
// word interleave within 8-groups: (w, w+4) adjacent
__device__ __forceinline__ int kslot(int w) {
    return (w & ~7) + 2 * (w & 3) + ((w >> 2) & 1);
}
// element permutation for V^T rows so contiguous copy yields kslot word order
__device__ __forceinline__ int eperm(int t) {
    int w = (t >> 1) & 7;
    int sl = 2 * (w & 3) + ((w >> 2) & 1);
    return (t & ~15) + sl * 2 + (t & 1);
}
__device__ __forceinline__ uint32_t smem_u32(const void* p) {
    uint32_t a;
    asm("{ .reg .u64 t; cvta.to.shared.u64 t, %1; cvt.u32.u64 %0, t; }" : "=r"(a) : "l"(p));
    return a;
}
#define CP16(dst, src) \
    asm volatile("cp.async.cg.shared.global [%0], [%1], 16;" :: "r"(dst), "l"(src))
#define CP_COMMIT() asm volatile("cp.async.commit_group;" ::: "memory")
#define CP_WAIT0()  asm volatile("cp.async.wait_group 0;" ::: "memory")

// ================= Kernel 0: W split -> bf16 words (unchanged layout) =================
__global__ void wsplit_kernel(const float* __restrict__ wq,
                              const float* __restrict__ wk,
                              const float* __restrict__ wv) {
    const int which = blockIdx.y, kt = blockIdx.x;
    const float* w = (which == 0) ? wq : (which == 1) ? wk : wv;
    const int tid = threadIdx.x;
#pragma unroll
    for (int i = 0; i < 4; i++) {
        int e = tid + i * 256;        // 0..1023 words
        int n = e & 63, wp = e >> 6;  // wp 0..15
        float x0 = w[(size_t)(kt * 32 + 2 * wp) * Hn + n];
        float x1 = w[(size_t)(kt * 32 + 2 * wp + 1) * Hn + n];
        uint32_t hw, lw;
        spb2(x0, x1, hw, lw);
        int dst = ((which * 32 + kt) * 64 + n) * 16 + kslot(wp);
        g_whi[dst] = hw;
        g_wlo[dst] = lw;
    }
}

// ================= Kernel 1: fused QKV projection (SMEM-free) =================
// grid 256 (M_TILE=128), block 256 (8 warps, each m16 x n192).
// A fragments direct from x (register prefetch), B fragments direct from g_whi/g_wlo.
__global__ __launch_bounds__(256) void qkv_kernel(const float* __restrict__ x)
{
    const int m0 = blockIdx.x * 128;
    const int tid = threadIdx.x;
    const int wid = tid >> 5, lane = tid & 31;
    const int lr = lane >> 2, lc = lane & 3;
    const int r0 = m0 + wid * 16 + lr;      // rows r0 and r0+8

    float acc[3][8][4];
#pragma unroll
    for (int wch = 0; wch < 3; wch++)
#pragma unroll
        for (int nt = 0; nt < 8; nt++)
#pragma unroll
            for (int i = 0; i < 4; i++) acc[wch][nt][i] = 0.f;

    float2 pa[2][4];
#pragma unroll
    for (int c = 0; c < 2; c++) {
        int k0 = c * 16 + 2 * lc;
        pa[c][0] = *(const float2*)&x[(size_t)r0 * Cn + k0];
        pa[c][1] = *(const float2*)&x[(size_t)(r0 + 8) * Cn + k0];
        pa[c][2] = *(const float2*)&x[(size_t)r0 * Cn + k0 + 8];
        pa[c][3] = *(const float2*)&x[(size_t)(r0 + 8) * Cn + k0 + 8];
    }

    for (int kt = 0; kt < 32; kt++) {
        float2 cur[2][4];
#pragma unroll
        for (int c = 0; c < 2; c++)
#pragma unroll
            for (int j = 0; j < 4; j++) cur[c][j] = pa[c][j];

        if (kt < 31) {
#pragma unroll
            for (int c = 0; c < 2; c++) {
                int k0 = (kt + 1) * 32 + c * 16 + 2 * lc;
                pa[c][0] = *(const float2*)&x[(size_t)r0 * Cn + k0];
                pa[c][1] = *(const float2*)&x[(size_t)(r0 + 8) * Cn + k0];
                pa[c][2] = *(const float2*)&x[(size_t)r0 * Cn + k0 + 8];
                pa[c][3] = *(const float2*)&x[(size_t)(r0 + 8) * Cn + k0 + 8];
            }
        }

#pragma unroll
        for (int c = 0; c < 2; c++) {
            uint32_t ah[4], al[4];
#pragma unroll
            for (int j = 0; j < 4; j++)
                spb2(cur[c][j].x, cur[c][j].y, ah[j], al[j]);
#pragma unroll
            for (int wch = 0; wch < 3; wch++) {
#pragma unroll
                for (int nt = 0; nt < 8; nt++) {
                    int idx = (((wch * 32 + kt) * 64) + nt * 8 + lr) * 16 + c * 8 + 2 * lc;
                    uint2 bh = *(const uint2*)&g_whi[idx];
                    uint2 bl = *(const uint2*)&g_wlo[idx];
                    mmab(acc[wch][nt], ah[0], ah[1], ah[2], ah[3], bh.x, bh.y);
                    mmab(acc[wch][nt], ah[0], ah[1], ah[2], ah[3], bl.x, bl.y);
                    mmab(acc[wch][nt], al[0], al[1], al[2], al[3], bh.x, bh.y);
                }
            }
        }
    }

    // Epilogue: pre-split / pre-pack by output kind
#pragma unroll
    for (int rr = 0; rr < 2; rr++) {
        int row = m0 + wid * 16 + rr * 8 + lr;
#pragma unroll
        for (int wch = 0; wch < 3; wch++)
#pragma unroll
            for (int nt = 0; nt < 8; nt++) {
                float v0 = acc[wch][nt][rr * 2 + 0];
                float v1 = acc[wch][nt][rr * 2 + 1];
                int col0 = nt * 8 + 2 * lc;
                int sl = kslot(nt * 4 + lc);
                if (wch == 0) {
                    uint32_t hw, lw;
                    spb2(v0 * 0.125f, v1 * 0.125f, hw, lw);
                    g_qhi[(size_t)row * 32 + sl] = hw;
                    g_qlo[(size_t)row * 32 + sl] = lw;
                } else if (wch == 1) {
                    uint32_t hw, lw;
                    spb2(v0, v1, hw, lw);
                    g_khi[(size_t)row * 32 + sl] = hw;
                    g_klo[(size_t)row * 32 + sl] = lw;
                } else {
                    int bb = row >> 11, t = row & 2047;
                    int ep = eperm(t);
                    unsigned short h0 = b16(v0);
                    unsigned short l0 = b16(v0 - fb16(h0));
                    unsigned short h1 = b16(v1);
                    unsigned short l1 = b16(v1 - fb16(h1));
                    g_vhiT[(size_t)(bb * Hn + col0) * Tn + ep] = h0;
                    g_vloT[(size_t)(bb * Hn + col0) * Tn + ep] = l0;
                    g_vhiT[(size_t)(bb * Hn + col0 + 1) * Tn + ep] = h1;
                    g_vloT[(size_t)(bb * Hn + col0 + 1) * Tn + ep] = l1;
                }
            }
    }
}

// ================= Kernel 2: flash attention (register P, Q_TILE=128) =================
// grid 256 (heavy-first), block 256 (8 warps, each m16 x n64). KV_TILE=64.
// SMEM: K/V hi/lo only, 40960 B. P lives in registers (FA2 layout identity).
__global__ __launch_bounds__(256) void attn_kernel(float* __restrict__ out)
{
    __shared__ __align__(16) uint32_t Kh[64 * 40];   // [s][kslot(h/2)] stride 40
    __shared__ __align__(16) uint32_t Kl[64 * 40];
    __shared__ __align__(16) uint32_t Vh[64 * 40];   // [h][kslot(s/2)]
    __shared__ __align__(16) uint32_t Vl[64 * 40];

    const int qt = 15 - (blockIdx.x >> 4);
    const int b  = blockIdx.x & 15;
    const int q0 = qt * 128;
    const size_t bT = (size_t)b * Tn;
    const int tid = threadIdx.x;
    const int wid = tid >> 5, lane = tid & 31;
    const int lr = lane >> 2, lc = lane & 3;
    const int r0l = wid * 16 + lr, r1l = r0l + 8;    // local q rows (0..127)

    const uint32_t KhA = smem_u32(Kh), KlA = smem_u32(Kl);
    const uint32_t VhA = smem_u32(Vh), VlA = smem_u32(Vl);

    // Q fragments: pre-split, pre-packed words straight from global
    uint32_t qah[4][4], qal[4][4];
#pragma unroll
    for (int c = 0; c < 4; c++) {
        uint2 h0 = *(const uint2*)&g_qhi[(bT + q0 + r0l) * 32 + c * 8 + 2 * lc];
        uint2 h1 = *(const uint2*)&g_qhi[(bT + q0 + r1l) * 32 + c * 8 + 2 * lc];
        uint2 l0 = *(const uint2*)&g_qlo[(bT + q0 + r0l) * 32 + c * 8 + 2 * lc];
        uint2 l1 = *(const uint2*)&g_qlo[(bT + q0 + r1l) * 32 + c * 8 + 2 * lc];
        qah[c][0] = h0.x; qah[c][1] = h1.x; qah[c][2] = h0.y; qah[c][3] = h1.y;
        qal[c][0] = l0.x; qal[c][1] = l1.x; qal[c][2] = l0.y; qal[c][3] = l1.y;
    }

    float o[8][4];
    float mrow[2] = { -1e30f, -1e30f };
    float lrow[2] = { 0.f, 0.f };
#pragma unroll
    for (int nt = 0; nt < 8; nt++)
#pragma unroll
        for (int i = 0; i < 4; i++) o[nt][i] = 0.f;

    const int n_iter = 2 * qt + 2;
    for (int st = 0; st < n_iter; st++) {
        const int s0 = st * 64;
        __syncthreads();  // previous iteration's K/V reads complete

        // cp.async fill: 8 warps over 4 arrays; warp w -> array w>>1, rows (w&1)*32..+31.
        // 32 rows x 8 chunks of 16B = 256 chunks per warp.
        {
            int arr = wid >> 1, half = wid & 1;
#pragma unroll
            for (int i = 0; i < 8; i++) {
                int c = lane + i * 32;            // 0..255
                int row = half * 32 + (c >> 3), ch = c & 7;
                if (arr == 0)
                    CP16(KhA + row * 160 + ch * 16,
                         g_khi + (bT + s0 + row) * 32 + ch * 4);
                else if (arr == 1)
                    CP16(KlA + row * 160 + ch * 16,
                         g_klo + (bT + s0 + row) * 32 + ch * 4);
                else if (arr == 2)
                    CP16(VhA + row * 160 + ch * 16,
                         g_vhiT + (size_t)(b * Hn + row) * Tn + s0 + ch * 8);
                else
                    CP16(VlA + row * 160 + ch * 16,
                         g_vloT + (size_t)(b * Hn + row) * Tn + s0 + ch * 8);
            }
        }
        CP_COMMIT();
        CP_WAIT0();
        __syncthreads();

        // ---- S = Q K^T ----
        float sacc[8][4];
#pragma unroll
        for (int nt = 0; nt < 8; nt++)
#pragma unroll
            for (int i = 0; i < 4; i++) sacc[nt][i] = 0.f;

#pragma unroll
        for (int c = 0; c < 4; c++) {
#pragma unroll
            for (int nt = 0; nt < 8; nt++) {
                uint2 bh = *(const uint2*)&Kh[(nt * 8 + lr) * 40 + c * 8 + 2 * lc];
                uint2 bl = *(const uint2*)&Kl[(nt * 8 + lr) * 40 + c * 8 + 2 * lc];
                mmab(sacc[nt], qah[c][0], qah[c][1], qah[c][2], qah[c][3], bh.x, bh.y);
                mmab(sacc[nt], qah[c][0], qah[c][1], qah[c][2], qah[c][3], bl.x, bl.y);
                mmab(sacc[nt], qal[c][0], qal[c][1], qal[c][2], qal[c][3], bh.x, bh.y);
            }
        }

        // ---- causal mask (tiles overlapping the diagonal) ----
        if (st >= 2 * qt) {
            int r0g = q0 + r0l, r1g = q0 + r1l;
#pragma unroll
            for (int nt = 0; nt < 8; nt++) {
                int cg = s0 + nt * 8 + 2 * lc;
                if (cg > r0g)     sacc[nt][0] = -1e30f;
                if (cg + 1 > r0g) sacc[nt][1] = -1e30f;
                if (cg > r1g)     sacc[nt][2] = -1e30f;
                if (cg + 1 > r1g) sacc[nt][3] = -1e30f;
            }
        }

        // ---- online softmax ----
        float mx0 = -1e30f, mx1 = -1e30f;
#pragma unroll
        for (int nt = 0; nt < 8; nt++) {
            mx0 = fmaxf(mx0, fmaxf(sacc[nt][0], sacc[nt][1]));
            mx1 = fmaxf(mx1, fmaxf(sacc[nt][2], sacc[nt][3]));
        }
        mx0 = fmaxf(mx0, __shfl_xor_sync(0xffffffffu, mx0, 1));
        mx0 = fmaxf(mx0, __shfl_xor_sync(0xffffffffu, mx0, 2));
        mx1 = fmaxf(mx1, __shfl_xor_sync(0xffffffffu, mx1, 1));
        mx1 = fmaxf(mx1, __shfl_xor_sync(0xffffffffu, mx1, 2));

        float mn0 = fmaxf(mrow[0], mx0), mn1 = fmaxf(mrow[1], mx1);
        float f0 = __expf(mrow[0] - mn0), f1 = __expf(mrow[1] - mn1);
        mrow[0] = mn0; mrow[1] = mn1;

        float sum0 = 0.f, sum1 = 0.f;
#pragma unroll
        for (int nt = 0; nt < 8; nt++) {
            sacc[nt][0] = __expf(sacc[nt][0] - mn0);
            sacc[nt][1] = __expf(sacc[nt][1] - mn0);
            sacc[nt][2] = __expf(sacc[nt][2] - mn1);
            sacc[nt][3] = __expf(sacc[nt][3] - mn1);
            sum0 += sacc[nt][0] + sacc[nt][1];
            sum1 += sacc[nt][2] + sacc[nt][3];
        }
        sum0 += __shfl_xor_sync(0xffffffffu, sum0, 1);
        sum0 += __shfl_xor_sync(0xffffffffu, sum0, 2);
        sum1 += __shfl_xor_sync(0xffffffffu, sum1, 1);
        sum1 += __shfl_xor_sync(0xffffffffu, sum1, 2);
        lrow[0] = lrow[0] * f0 + sum0;
        lrow[1] = lrow[1] * f1 + sum1;

#pragma unroll
        for (int nt = 0; nt < 8; nt++) {
            o[nt][0] *= f0; o[nt][1] *= f0;
            o[nt][2] *= f1; o[nt][3] *= f1;
        }

        // ---- O += P V, P taken directly from sacc registers (FA2 layout identity) ----
#pragma unroll
        for (int c = 0; c < 4; c++) {
            uint32_t ah[4], al[4];
            spb2(sacc[2 * c][0],     sacc[2 * c][1],     ah[0], al[0]);
            spb2(sacc[2 * c][2],     sacc[2 * c][3],     ah[1], al[1]);
            spb2(sacc[2 * c + 1][0], sacc[2 * c + 1][1], ah[2], al[2]);
            spb2(sacc[2 * c + 1][2], sacc[2 * c + 1][3], ah[3], al[3]);
#pragma unroll
            for (int nt = 0; nt < 8; nt++) {
                uint2 vh = *(const uint2*)&Vh[(nt * 8 + lr) * 40 + c * 8 + 2 * lc];
                uint2 vl = *(const uint2*)&Vl[(nt * 8 + lr) * 40 + c * 8 + 2 * lc];
                mmab(o[nt], ah[0], ah[1], ah[2], ah[3], vh.x, vh.y);
                mmab(o[nt], ah[0], ah[1], ah[2], ah[3], vl.x, vl.y);
                mmab(o[nt], al[0], al[1], al[2], al[3], vh.x, vh.y);
            }
        }
    }

    float inv0 = 1.0f / lrow[0], inv1 = 1.0f / lrow[1];
#pragma unroll
    for (int nt = 0; nt < 8; nt++) {
        int col = nt * 8 + 2 * lc;
        *(float2*)&out[(bT + q0 + r0l) * Hn + col] =
            make_float2(o[nt][0] * inv0, o[nt][1] * inv0);
        *(float2*)&out[(bT + q0 + r1l) * Hn + col] =
            make_float2(o[nt][2] * inv1, o[nt][3] * inv1);
    }
}

// ================= launch =================
extern "C" void kernel_launch(void* const* d_in, const int* in_sizes, int n_in,
                              void* d_out, int out_size)
{
    const float* x  = (const float*)d_in[0];
    const float* wq = (const float*)d_in[1];
    const float* wk = (const float*)d_in[2];
    const float* wv = (const float*)d_in[3];
    float* out = (float*)d_out;

    wsplit_kernel<<<dim3(32, 3), 256>>>(wq, wk, wv);
    qkv_kernel<<<256, 256>>>(x);
    attn_kernel<<<256, 256>>>(out);
}

// round 10
// speedup vs baseline: 1.8474x; 1.8474x over previous
#include <cuda_runtime.h>
#include <cstdint>

#define Bn 16
#define Tn 2048
#define Cn 1024
#define Hn 64

// ---------------- global scratch (pre-split bf16 operands) ----------------
__device__ uint32_t g_qhi[Bn * Tn * 32];   // Q scaled, bf16-pair words [t][kslot(h/2)]
__device__ uint32_t g_qlo[Bn * Tn * 32];
__device__ uint32_t g_khi[Bn * Tn * 32];   // K words [t][kslot(h/2)]
__device__ uint32_t g_klo[Bn * Tn * 32];
__device__ unsigned short g_vhiT[Bn * Hn * Tn];  // V^T bf16 [b][h][eperm(t)]
__device__ unsigned short g_vloT[Bn * Hn * Tn];
__device__ uint32_t g_whi[3 * 32 * 64 * 16];     // W words [which][kt][n][kslot(k/2)]
__device__ uint32_t g_wlo[3 * 32 * 64 * 16];

// ---------------- helpers ----------------
__device__ __forceinline__ unsigned short b16(float x) {
    unsigned short h;
    asm("cvt.rn.bf16.f32 %0, %1;" : "=h"(h) : "f"(x));
    return h;
}
__device__ __forceinline__ float fb16(unsigned short h) {
    return __uint_as_float((uint32_t)h << 16);
}
__device__ __forceinline__ uint32_t pkb(unsigned short lo, unsigned short hi) {
    uint32_t r;
    asm("mov.b32 %0, {%1, %2};" : "=r"(r) : "h"(lo), "h"(hi));
    return r;
}
// split pair (x0 = k-even, x1 = k-odd) into hi-word and lo-word
__device__ __forceinline__ void spb2(float x0, float x1, uint32_t& hw, uint32_t& lw) {
    unsigned short h0 = b16(x0), h1 = b16(x1);
    unsigned short l0 = b16(x0 - fb16(h0)), l1 = b16(x1 - fb16(h1));
    hw = pkb(h0, h1);
    lw = pkb(l0, l1);
}
// bf16 m16n8k16 mma, fp32 accum
__device__ __forceinline__ void mmab(float c[4],
                                     uint32_t a0, uint32_t a1, uint32_t a2, uint32_t a3,
                                     uint32_t b0, uint32_t b1) {
    asm volatile(
        "mma.sync.aligned.m16n8k16.row.col.f32.bf16.bf16.f32 "
        "{%0,%1,%2,%3}, {%4,%5,%6,%7}, {%8,%9}, {%0,%1,%2,%3};"
        : "+f"(c[0]), "+f"(c[1]), "+f"(c[2]), "+f"(c[3])
        : "r"(a0), "r"(a1), "r"(a2), "r"(a3), "r"(b0), "r"(b1));
}
// word interleave within 8-groups: (w, w+4) adjacent
__device__ __forceinline__ int kslot(int w) {
    return (w & ~7) + 2 * (w & 3) + ((w >> 2) & 1);
}
// element permutation for V^T rows so contiguous copy yields kslot word order
__device__ __forceinline__ int eperm(int t) {
    int w = (t >> 1) & 7;
    int sl = 2 * (w & 3) + ((w >> 2) & 1);
    return (t & ~15) + sl * 2 + (t & 1);
}
__device__ __forceinline__ uint32_t smem_u32(const void* p) {
    uint32_t a;
    asm("{ .reg .u64 t; cvta.to.shared.u64 t, %1; cvt.u32.u64 %0, t; }" : "=r"(a) : "l"(p));
    return a;
}
#define CP16(dst, src) \
    asm volatile("cp.async.cg.shared.global [%0], [%1], 16;" :: "r"(dst), "l"(src))
#define CP_COMMIT() asm volatile("cp.async.commit_group;" ::: "memory")
#define CP_WAIT0()  asm volatile("cp.async.wait_group 0;" ::: "memory")

// ================= Kernel 0: W split -> bf16 words =================
__global__ void wsplit_kernel(const float* __restrict__ wq,
                              const float* __restrict__ wk,
                              const float* __restrict__ wv) {
    const int which = blockIdx.y, kt = blockIdx.x;
    const float* w = (which == 0) ? wq : (which == 1) ? wk : wv;
    const int tid = threadIdx.x;
#pragma unroll
    for (int i = 0; i < 4; i++) {
        int e = tid + i * 256;        // 0..1023 words
        int n = e & 63, wp = e >> 6;  // wp 0..15
        float x0 = w[(size_t)(kt * 32 + 2 * wp) * Hn + n];
        float x1 = w[(size_t)(kt * 32 + 2 * wp + 1) * Hn + n];
        uint32_t hw, lw;
        spb2(x0, x1, hw, lw);
        int dst = ((which * 32 + kt) * 64 + n) * 16 + kslot(wp);
        g_whi[dst] = hw;
        g_wlo[dst] = lw;
    }
}

// ================= Kernel 1: QKV projection (R8 SMEM-staged version) =================
// grid (256, 3), block 128 (4 warps, m32 x n64). M_TILE=128, K chunks of 32.
__global__ __launch_bounds__(128, 4) void qkv_kernel(const float* __restrict__ x)
{
    __shared__ __align__(16) float As[128 * 40];     // fp32 [m][k] pad 40
    __shared__ __align__(16) uint32_t Bh[64 * 24];   // words [n][kslot] stride 24
    __shared__ __align__(16) uint32_t Bl[64 * 24];

    const int which = blockIdx.y;
    const int m0 = blockIdx.x * 128;
    const int tid = threadIdx.x;
    const int wid = tid >> 5, lane = tid & 31;
    const int lr = lane >> 2, lc = lane & 3;

    const uint32_t AsA = smem_u32(As), BhA = smem_u32(Bh), BlA = smem_u32(Bl);

    float acc[2][8][4];
#pragma unroll
    for (int mt = 0; mt < 2; mt++)
#pragma unroll
        for (int nt = 0; nt < 8; nt++)
#pragma unroll
            for (int i = 0; i < 4; i++) acc[mt][nt][i] = 0.f;

    for (int kt = 0; kt < Cn / 32; kt++) {
        // A fill: 128 rows x 8 chunks (32 fp32 = 128B) = 1024 chunks
#pragma unroll
        for (int l = 0; l < 8; l++) {
            int idx = tid + l * 128;
            int row = idx >> 3, ch = idx & 7;
            CP16(AsA + row * 160 + ch * 16,
                 x + (size_t)(m0 + row) * Cn + kt * 32 + ch * 4);
        }
        // B fill: Bh/Bl 64 rows x 4 chunks (16 words = 64B) each = 512 chunks total
        const size_t tb = (size_t)(which * 32 + kt) * 1024;
#pragma unroll
        for (int l = 0; l < 4; l++) {
            int idx = tid + l * 128;          // 0..511
            int sel = idx >> 8;               // 0: Bh, 1: Bl
            int r = idx & 255;
            int n = r >> 2, ch = r & 3;
            uint32_t dst = (sel ? BlA : BhA) + n * 96 + ch * 16;
            const uint32_t* src = (sel ? g_wlo : g_whi) + tb + n * 16 + ch * 4;
            CP16(dst, src);
        }
        CP_COMMIT();
        CP_WAIT0();
        __syncthreads();

#pragma unroll
        for (int c = 0; c < 2; c++) {         // two k16 chunks
            uint32_t ah[2][4], al[2][4];
#pragma unroll
            for (int mt = 0; mt < 2; mt++) {
                int rb = wid * 32 + mt * 16 + lr;
                float2 p0 = *(const float2*)&As[rb * 40 + c * 16 + 2 * lc];
                float2 p1 = *(const float2*)&As[(rb + 8) * 40 + c * 16 + 2 * lc];
                float2 p2 = *(const float2*)&As[rb * 40 + c * 16 + 8 + 2 * lc];
                float2 p3 = *(const float2*)&As[(rb + 8) * 40 + c * 16 + 8 + 2 * lc];
                spb2(p0.x, p0.y, ah[mt][0], al[mt][0]);
                spb2(p1.x, p1.y, ah[mt][1], al[mt][1]);
                spb2(p2.x, p2.y, ah[mt][2], al[mt][2]);
                spb2(p3.x, p3.y, ah[mt][3], al[mt][3]);
            }
#pragma unroll
            for (int nt = 0; nt < 8; nt++) {
                uint2 bh = *(const uint2*)&Bh[(nt * 8 + lr) * 24 + c * 8 + 2 * lc];
                uint2 bl = *(const uint2*)&Bl[(nt * 8 + lr) * 24 + c * 8 + 2 * lc];
#pragma unroll
                for (int mt = 0; mt < 2; mt++) {
                    mmab(acc[mt][nt], ah[mt][0], ah[mt][1], ah[mt][2], ah[mt][3], bh.x, bh.y);
                    mmab(acc[mt][nt], ah[mt][0], ah[mt][1], ah[mt][2], ah[mt][3], bl.x, bl.y);
                    mmab(acc[mt][nt], al[mt][0], al[mt][1], al[mt][2], al[mt][3], bh.x, bh.y);
                }
            }
        }
        __syncthreads();
    }

    // Epilogue: pre-split / pre-pack by output kind
#pragma unroll
    for (int mt = 0; mt < 2; mt++)
#pragma unroll
        for (int rr = 0; rr < 2; rr++) {
            int row = m0 + wid * 32 + mt * 16 + rr * 8 + lr;
#pragma unroll
            for (int nt = 0; nt < 8; nt++) {
                float v0 = acc[mt][nt][rr * 2 + 0];
                float v1 = acc[mt][nt][rr * 2 + 1];
                int col0 = nt * 8 + 2 * lc;
                int sl = kslot(nt * 4 + lc);
                if (which == 0) {
                    uint32_t hw, lw;
                    spb2(v0 * 0.125f, v1 * 0.125f, hw, lw);
                    g_qhi[(size_t)row * 32 + sl] = hw;
                    g_qlo[(size_t)row * 32 + sl] = lw;
                } else if (which == 1) {
                    uint32_t hw, lw;
                    spb2(v0, v1, hw, lw);
                    g_khi[(size_t)row * 32 + sl] = hw;
                    g_klo[(size_t)row * 32 + sl] = lw;
                } else {
                    int bb = row >> 11, t = row & 2047;
                    int ep = eperm(t);
                    unsigned short h0 = b16(v0);
                    unsigned short l0 = b16(v0 - fb16(h0));
                    unsigned short h1 = b16(v1);
                    unsigned short l1 = b16(v1 - fb16(h1));
                    g_vhiT[(size_t)(bb * Hn + col0) * Tn + ep] = h0;
                    g_vloT[(size_t)(bb * Hn + col0) * Tn + ep] = l0;
                    g_vhiT[(size_t)(bb * Hn + col0 + 1) * Tn + ep] = h1;
                    g_vloT[(size_t)(bb * Hn + col0 + 1) * Tn + ep] = l1;
                }
            }
        }
}

// ================= Kernel 2: flash attention (register P, Q_TILE=128) =================
// grid 256 (heavy-first), block 256 (8 warps, each m16 x n64). KV_TILE=64.
// SMEM: K/V hi/lo only, 40960 B. P lives in registers (FA2 layout identity).
__global__ __launch_bounds__(256) void attn_kernel(float* __restrict__ out)
{
    __shared__ __align__(16) uint32_t Kh[64 * 40];   // [s][kslot(h/2)] stride 40
    __shared__ __align__(16) uint32_t Kl[64 * 40];
    __shared__ __align__(16) uint32_t Vh[64 * 40];   // [h][kslot(s/2)]
    __shared__ __align__(16) uint32_t Vl[64 * 40];

    const int qt = 15 - (blockIdx.x >> 4);
    const int b  = blockIdx.x & 15;
    const int q0 = qt * 128;
    const size_t bT = (size_t)b * Tn;
    const int tid = threadIdx.x;
    const int wid = tid >> 5, lane = tid & 31;
    const int lr = lane >> 2, lc = lane & 3;
    const int r0l = wid * 16 + lr, r1l = r0l + 8;    // local q rows (0..127)

    const uint32_t KhA = smem_u32(Kh), KlA = smem_u32(Kl);
    const uint32_t VhA = smem_u32(Vh), VlA = smem_u32(Vl);

    // Q fragments: pre-split, pre-packed words straight from global
    uint32_t qah[4][4], qal[4][4];
#pragma unroll
    for (int c = 0; c < 4; c++) {
        uint2 h0 = *(const uint2*)&g_qhi[(bT + q0 + r0l) * 32 + c * 8 + 2 * lc];
        uint2 h1 = *(const uint2*)&g_qhi[(bT + q0 + r1l) * 32 + c * 8 + 2 * lc];
        uint2 l0 = *(const uint2*)&g_qlo[(bT + q0 + r0l) * 32 + c * 8 + 2 * lc];
        uint2 l1 = *(const uint2*)&g_qlo[(bT + q0 + r1l) * 32 + c * 8 + 2 * lc];
        qah[c][0] = h0.x; qah[c][1] = h1.x; qah[c][2] = h0.y; qah[c][3] = h1.y;
        qal[c][0] = l0.x; qal[c][1] = l1.x; qal[c][2] = l0.y; qal[c][3] = l1.y;
    }

    float o[8][4];
    float mrow[2] = { -1e30f, -1e30f };
    float lrow[2] = { 0.f, 0.f };
#pragma unroll
    for (int nt = 0; nt < 8; nt++)
#pragma unroll
        for (int i = 0; i < 4; i++) o[nt][i] = 0.f;

    const int n_iter = 2 * qt + 2;
    for (int st = 0; st < n_iter; st++) {
        const int s0 = st * 64;
        __syncthreads();  // previous iteration's K/V reads complete

        // cp.async fill: 8 warps over 4 arrays; warp w -> array w>>1, rows (w&1)*32..+31.
        // 32 rows x 8 chunks of 16B = 256 chunks per warp.
        {
            int arr = wid >> 1, half = wid & 1;
#pragma unroll
            for (int i = 0; i < 8; i++) {
                int c = lane + i * 32;            // 0..255
                int row = half * 32 + (c >> 3), ch = c & 7;
                if (arr == 0)
                    CP16(KhA + row * 160 + ch * 16,
                         g_khi + (bT + s0 + row) * 32 + ch * 4);
                else if (arr == 1)
                    CP16(KlA + row * 160 + ch * 16,
                         g_klo + (bT + s0 + row) * 32 + ch * 4);
                else if (arr == 2)
                    CP16(VhA + row * 160 + ch * 16,
                         g_vhiT + (size_t)(b * Hn + row) * Tn + s0 + ch * 8);
                else
                    CP16(VlA + row * 160 + ch * 16,
                         g_vloT + (size_t)(b * Hn + row) * Tn + s0 + ch * 8);
            }
        }
        CP_COMMIT();
        CP_WAIT0();
        __syncthreads();

        // ---- S = Q K^T ----
        float sacc[8][4];
#pragma unroll
        for (int nt = 0; nt < 8; nt++)
#pragma unroll
            for (int i = 0; i < 4; i++) sacc[nt][i] = 0.f;

#pragma unroll
        for (int c = 0; c < 4; c++) {
#pragma unroll
            for (int nt = 0; nt < 8; nt++) {
                uint2 bh = *(const uint2*)&Kh[(nt * 8 + lr) * 40 + c * 8 + 2 * lc];
                uint2 bl = *(const uint2*)&Kl[(nt * 8 + lr) * 40 + c * 8 + 2 * lc];
                mmab(sacc[nt], qah[c][0], qah[c][1], qah[c][2], qah[c][3], bh.x, bh.y);
                mmab(sacc[nt], qah[c][0], qah[c][1], qah[c][2], qah[c][3], bl.x, bl.y);
                mmab(sacc[nt], qal[c][0], qal[c][1], qal[c][2], qal[c][3], bh.x, bh.y);
            }
        }

        // ---- causal mask (tiles overlapping the diagonal) ----
        if (st >= 2 * qt) {
            int r0g = q0 + r0l, r1g = q0 + r1l;
#pragma unroll
            for (int nt = 0; nt < 8; nt++) {
                int cg = s0 + nt * 8 + 2 * lc;
                if (cg > r0g)     sacc[nt][0] = -1e30f;
                if (cg + 1 > r0g) sacc[nt][1] = -1e30f;
                if (cg > r1g)     sacc[nt][2] = -1e30f;
                if (cg + 1 > r1g) sacc[nt][3] = -1e30f;
            }
        }

        // ---- online softmax ----
        float mx0 = -1e30f, mx1 = -1e30f;
#pragma unroll
        for (int nt = 0; nt < 8; nt++) {
            mx0 = fmaxf(mx0, fmaxf(sacc[nt][0], sacc[nt][1]));
            mx1 = fmaxf(mx1, fmaxf(sacc[nt][2], sacc[nt][3]));
        }
        mx0 = fmaxf(mx0, __shfl_xor_sync(0xffffffffu, mx0, 1));
        mx0 = fmaxf(mx0, __shfl_xor_sync(0xffffffffu, mx0, 2));
        mx1 = fmaxf(mx1, __shfl_xor_sync(0xffffffffu, mx1, 1));
        mx1 = fmaxf(mx1, __shfl_xor_sync(0xffffffffu, mx1, 2));

        float mn0 = fmaxf(mrow[0], mx0), mn1 = fmaxf(mrow[1], mx1);
        float f0 = __expf(mrow[0] - mn0), f1 = __expf(mrow[1] - mn1);
        mrow[0] = mn0; mrow[1] = mn1;

        float sum0 = 0.f, sum1 = 0.f;
#pragma unroll
        for (int nt = 0; nt < 8; nt++) {
            sacc[nt][0] = __expf(sacc[nt][0] - mn0);
            sacc[nt][1] = __expf(sacc[nt][1] - mn0);
            sacc[nt][2] = __expf(sacc[nt][2] - mn1);
            sacc[nt][3] = __expf(sacc[nt][3] - mn1);
            sum0 += sacc[nt][0] + sacc[nt][1];
            sum1 += sacc[nt][2] + sacc[nt][3];
        }
        sum0 += __shfl_xor_sync(0xffffffffu, sum0, 1);
        sum0 += __shfl_xor_sync(0xffffffffu, sum0, 2);
        sum1 += __shfl_xor_sync(0xffffffffu, sum1, 1);
        sum1 += __shfl_xor_sync(0xffffffffu, sum1, 2);
        lrow[0] = lrow[0] * f0 + sum0;
        lrow[1] = lrow[1] * f1 + sum1;

#pragma unroll
        for (int nt = 0; nt < 8; nt++) {
            o[nt][0] *= f0; o[nt][1] *= f0;
            o[nt][2] *= f1; o[nt][3] *= f1;
        }

        // ---- O += P V, P taken directly from sacc registers (FA2 layout identity) ----
#pragma unroll
        for (int c = 0; c < 4; c++) {
            uint32_t ah[4], al[4];
            spb2(sacc[2 * c][0],     sacc[2 * c][1],     ah[0], al[0]);
            spb2(sacc[2 * c][2],     sacc[2 * c][3],     ah[1], al[1]);
            spb2(sacc[2 * c + 1][0], sacc[2 * c + 1][1], ah[2], al[2]);
            spb2(sacc[2 * c + 1][2], sacc[2 * c + 1][3], ah[3], al[3]);
#pragma unroll
            for (int nt = 0; nt < 8; nt++) {
                uint2 vh = *(const uint2*)&Vh[(nt * 8 + lr) * 40 + c * 8 + 2 * lc];
                uint2 vl = *(const uint2*)&Vl[(nt * 8 + lr) * 40 + c * 8 + 2 * lc];
                mmab(o[nt], ah[0], ah[1], ah[2], ah[3], vh.x, vh.y);
                mmab(o[nt], ah[0], ah[1], ah[2], ah[3], vl.x, vl.y);
                mmab(o[nt], al[0], al[1], al[2], al[3], vh.x, vh.y);
            }
        }
    }

    float inv0 = 1.0f / lrow[0], inv1 = 1.0f / lrow[1];
#pragma unroll
    for (int nt = 0; nt < 8; nt++) {
        int col = nt * 8 + 2 * lc;
        *(float2*)&out[(bT + q0 + r0l) * Hn + col] =
            make_float2(o[nt][0] * inv0, o[nt][1] * inv0);
        *(float2*)&out[(bT + q0 + r1l) * Hn + col] =
            make_float2(o[nt][2] * inv1, o[nt][3] * inv1);
    }
}

// ================= launch =================
extern "C" void kernel_launch(void* const* d_in, const int* in_sizes, int n_in,
                              void* d_out, int out_size)
{
    const float* x  = (const float*)d_in[0];
    const float* wq = (const float*)d_in[1];
    const float* wk = (const float*)d_in[2];
    const float* wv = (const float*)d_in[3];
    float* out = (float*)d_out;

    wsplit_kernel<<<dim3(32, 3), 256>>>(wq, wk, wv);
    qkv_kernel<<<dim3((Bn * Tn) / 128, 3), 128>>>(x);
    attn_kernel<<<256, 256>>>(out);
}

// round 11
// speedup vs baseline: 2.0042x; 1.0849x over previous
#include <cuda_runtime.h>
#include <cstdint>

#define Bn 16
#define Tn 2048
#define Cn 1024
#define Hn 64

// ---------------- global scratch (pre-split bf16 operands) ----------------
__device__ uint32_t g_qhi[Bn * Tn * 32];   // Q scaled, bf16-pair words [t][kslot(h/2)]
__device__ uint32_t g_qlo[Bn * Tn * 32];
__device__ uint32_t g_khi[Bn * Tn * 32];   // K words [t][kslot(h/2)]
__device__ uint32_t g_klo[Bn * Tn * 32];
__device__ unsigned short g_vhiT[Bn * Hn * Tn];  // V^T bf16 [b][h][eperm(t)]
__device__ unsigned short g_vloT[Bn * Hn * Tn];
__device__ uint32_t g_whi[3 * 32 * 64 * 16];     // W words [which][kt][n][kslot(k/2)]
__device__ uint32_t g_wlo[3 * 32 * 64 * 16];

// ---------------- helpers ----------------
__device__ __forceinline__ unsigned short b16(float x) {
    unsigned short h;
    asm("cvt.rn.bf16.f32 %0, %1;" : "=h"(h) : "f"(x));
    return h;
}
__device__ __forceinline__ float fb16(unsigned short h) {
    return __uint_as_float((uint32_t)h << 16);
}
__device__ __forceinline__ uint32_t pkb(unsigned short lo, unsigned short hi) {
    uint32_t r;
    asm("mov.b32 %0, {%1, %2};" : "=r"(r) : "h"(lo), "h"(hi));
    return r;
}
// split pair (x0 = k-even, x1 = k-odd) into hi-word and lo-word
__device__ __forceinline__ void spb2(float x0, float x1, uint32_t& hw, uint32_t& lw) {
    unsigned short h0 = b16(x0), h1 = b16(x1);
    unsigned short l0 = b16(x0 - fb16(h0)), l1 = b16(x1 - fb16(h1));
    hw = pkb(h0, h1);
    lw = pkb(l0, l1);
}
// bf16 m16n8k16 mma, fp32 accum
__device__ __forceinline__ void mmab(float c[4],
                                     uint32_t a0, uint32_t a1, uint32_t a2, uint32_t a3,
                                     uint32_t b0, uint32_t b1) {
    asm volatile(
        "mma.sync.aligned.m16n8k16.row.col.f32.bf16.bf16.f32 "
        "{%0,%1,%2,%3}, {%4,%5,%6,%7}, {%8,%9}, {%0,%1,%2,%3};"
        : "+f"(c[0]), "+f"(c[1]), "+f"(c[2]), "+f"(c[3])
        : "r"(a0), "r"(a1), "r"(a2), "r"(a3), "r"(b0), "r"(b1));
}
// word interleave within 8-groups: (w, w+4) adjacent
__device__ __forceinline__ int kslot(int w) {
    return (w & ~7) + 2 * (w & 3) + ((w >> 2) & 1);
}
// element permutation for V^T rows so contiguous copy yields kslot word order
__device__ __forceinline__ int eperm(int t) {
    int w = (t >> 1) & 7;
    int sl = 2 * (w & 3) + ((w >> 2) & 1);
    return (t & ~15) + sl * 2 + (t & 1);
}
__device__ __forceinline__ uint32_t smem_u32(const void* p) {
    uint32_t a;
    asm("{ .reg .u64 t; cvta.to.shared.u64 t, %1; cvt.u32.u64 %0, t; }" : "=r"(a) : "l"(p));
    return a;
}
#define CP16(dst, src) \
    asm volatile("cp.async.cg.shared.global [%0], [%1], 16;" :: "r"(dst), "l"(src))
#define CP_COMMIT() asm volatile("cp.async.commit_group;" ::: "memory")
#define CP_WAIT0()  asm volatile("cp.async.wait_group 0;" ::: "memory")
#define CP_WAIT1()  asm volatile("cp.async.wait_group 1;" ::: "memory")

// ================= Kernel 0: W split -> bf16 words =================
__global__ void wsplit_kernel(const float* __restrict__ wq,
                              const float* __restrict__ wk,
                              const float* __restrict__ wv) {
    const int which = blockIdx.y, kt = blockIdx.x;
    const float* w = (which == 0) ? wq : (which == 1) ? wk : wv;
    const int tid = threadIdx.x;
#pragma unroll
    for (int i = 0; i < 4; i++) {
        int e = tid + i * 256;        // 0..1023 words
        int n = e & 63, wp = e >> 6;  // wp 0..15
        float x0 = w[(size_t)(kt * 32 + 2 * wp) * Hn + n];
        float x1 = w[(size_t)(kt * 32 + 2 * wp + 1) * Hn + n];
        uint32_t hw, lw;
        spb2(x0, x1, hw, lw);
        int dst = ((which * 32 + kt) * 64 + n) * 16 + kslot(wp);
        g_whi[dst] = hw;
        g_wlo[dst] = lw;
    }
}

// ================= Kernel 1: QKV projection (R10 known-good, untouched) =================
// grid (256, 3), block 128 (4 warps, m32 x n64). M_TILE=128, K chunks of 32.
__global__ __launch_bounds__(128, 4) void qkv_kernel(const float* __restrict__ x)
{
    __shared__ __align__(16) float As[128 * 40];     // fp32 [m][k] pad 40
    __shared__ __align__(16) uint32_t Bh[64 * 24];   // words [n][kslot] stride 24
    __shared__ __align__(16) uint32_t Bl[64 * 24];

    const int which = blockIdx.y;
    const int m0 = blockIdx.x * 128;
    const int tid = threadIdx.x;
    const int wid = tid >> 5, lane = tid & 31;
    const int lr = lane >> 2, lc = lane & 3;

    const uint32_t AsA = smem_u32(As), BhA = smem_u32(Bh), BlA = smem_u32(Bl);

    float acc[2][8][4];
#pragma unroll
    for (int mt = 0; mt < 2; mt++)
#pragma unroll
        for (int nt = 0; nt < 8; nt++)
#pragma unroll
            for (int i = 0; i < 4; i++) acc[mt][nt][i] = 0.f;

    for (int kt = 0; kt < Cn / 32; kt++) {
        // A fill: 128 rows x 8 chunks (32 fp32 = 128B) = 1024 chunks
#pragma unroll
        for (int l = 0; l < 8; l++) {
            int idx = tid + l * 128;
            int row = idx >> 3, ch = idx & 7;
            CP16(AsA + row * 160 + ch * 16,
                 x + (size_t)(m0 + row) * Cn + kt * 32 + ch * 4);
        }
        // B fill: Bh/Bl 64 rows x 4 chunks (16 words = 64B) each = 512 chunks total
        const size_t tb = (size_t)(which * 32 + kt) * 1024;
#pragma unroll
        for (int l = 0; l < 4; l++) {
            int idx = tid + l * 128;          // 0..511
            int sel = idx >> 8;               // 0: Bh, 1: Bl
            int r = idx & 255;
            int n = r >> 2, ch = r & 3;
            uint32_t dst = (sel ? BlA : BhA) + n * 96 + ch * 16;
            const uint32_t* src = (sel ? g_wlo : g_whi) + tb + n * 16 + ch * 4;
            CP16(dst, src);
        }
        CP_COMMIT();
        CP_WAIT0();
        __syncthreads();

#pragma unroll
        for (int c = 0; c < 2; c++) {         // two k16 chunks
            uint32_t ah[2][4], al[2][4];
#pragma unroll
            for (int mt = 0; mt < 2; mt++) {
                int rb = wid * 32 + mt * 16 + lr;
                float2 p0 = *(const float2*)&As[rb * 40 + c * 16 + 2 * lc];
                float2 p1 = *(const float2*)&As[(rb + 8) * 40 + c * 16 + 2 * lc];
                float2 p2 = *(const float2*)&As[rb * 40 + c * 16 + 8 + 2 * lc];
                float2 p3 = *(const float2*)&As[(rb + 8) * 40 + c * 16 + 8 + 2 * lc];
                spb2(p0.x, p0.y, ah[mt][0], al[mt][0]);
                spb2(p1.x, p1.y, ah[mt][1], al[mt][1]);
                spb2(p2.x, p2.y, ah[mt][2], al[mt][2]);
                spb2(p3.x, p3.y, ah[mt][3], al[mt][3]);
            }
#pragma unroll
            for (int nt = 0; nt < 8; nt++) {
                uint2 bh = *(const uint2*)&Bh[(nt * 8 + lr) * 24 + c * 8 + 2 * lc];
                uint2 bl = *(const uint2*)&Bl[(nt * 8 + lr) * 24 + c * 8 + 2 * lc];
#pragma unroll
                for (int mt = 0; mt < 2; mt++) {
                    mmab(acc[mt][nt], ah[mt][0], ah[mt][1], ah[mt][2], ah[mt][3], bh.x, bh.y);
                    mmab(acc[mt][nt], ah[mt][0], ah[mt][1], ah[mt][2], ah[mt][3], bl.x, bl.y);
                    mmab(acc[mt][nt], al[mt][0], al[mt][1], al[mt][2], al[mt][3], bh.x, bh.y);
                }
            }
        }
        __syncthreads();
    }

    // Epilogue: pre-split / pre-pack by output kind
#pragma unroll
    for (int mt = 0; mt < 2; mt++)
#pragma unroll
        for (int rr = 0; rr < 2; rr++) {
            int row = m0 + wid * 32 + mt * 16 + rr * 8 + lr;
#pragma unroll
            for (int nt = 0; nt < 8; nt++) {
                float v0 = acc[mt][nt][rr * 2 + 0];
                float v1 = acc[mt][nt][rr * 2 + 1];
                int col0 = nt * 8 + 2 * lc;
                int sl = kslot(nt * 4 + lc);
                if (which == 0) {
                    uint32_t hw, lw;
                    spb2(v0 * 0.125f, v1 * 0.125f, hw, lw);
                    g_qhi[(size_t)row * 32 + sl] = hw;
                    g_qlo[(size_t)row * 32 + sl] = lw;
                } else if (which == 1) {
                    uint32_t hw, lw;
                    spb2(v0, v1, hw, lw);
                    g_khi[(size_t)row * 32 + sl] = hw;
                    g_klo[(size_t)row * 32 + sl] = lw;
                } else {
                    int bb = row >> 11, t = row & 2047;
                    int ep = eperm(t);
                    unsigned short h0 = b16(v0);
                    unsigned short l0 = b16(v0 - fb16(h0));
                    unsigned short h1 = b16(v1);
                    unsigned short l1 = b16(v1 - fb16(h1));
                    g_vhiT[(size_t)(bb * Hn + col0) * Tn + ep] = h0;
                    g_vloT[(size_t)(bb * Hn + col0) * Tn + ep] = l0;
                    g_vhiT[(size_t)(bb * Hn + col0 + 1) * Tn + ep] = h1;
                    g_vloT[(size_t)(bb * Hn + col0 + 1) * Tn + ep] = l1;
                }
            }
        }
}

// ================= Kernel 2: flash attention (register P + 2-stage K/V pipeline) =================
// grid 256 (heavy-first), block 256 (8 warps, each m16 x n64). Q_TILE=128, KV_TILE=64.
// Dynamic SMEM: 2 stages x 4 arrays x 64 x 40 words = 81920 B.
#define STG_W 10240   // words per stage
#define ARR_W 2560    // words per array (64 * 40)
__global__ __launch_bounds__(256) void attn_kernel(float* __restrict__ out)
{
    extern __shared__ __align__(16) uint32_t dsm[];

    const int qt = 15 - (blockIdx.x >> 4);
    const int b  = blockIdx.x & 15;
    const int q0 = qt * 128;
    const size_t bT = (size_t)b * Tn;
    const int tid = threadIdx.x;
    const int wid = tid >> 5, lane = tid & 31;
    const int lr = lane >> 2, lc = lane & 3;
    const int r0l = wid * 16 + lr, r1l = r0l + 8;    // local q rows (0..127)

    const uint32_t dsmA = smem_u32(dsm);
    const int arr = wid >> 1, half = wid & 1;        // fill ownership

    // Q fragments: pre-split, pre-packed words straight from global
    uint32_t qah[4][4], qal[4][4];
#pragma unroll
    for (int c = 0; c < 4; c++) {
        uint2 h0 = *(const uint2*)&g_qhi[(bT + q0 + r0l) * 32 + c * 8 + 2 * lc];
        uint2 h1 = *(const uint2*)&g_qhi[(bT + q0 + r1l) * 32 + c * 8 + 2 * lc];
        uint2 l0 = *(const uint2*)&g_qlo[(bT + q0 + r0l) * 32 + c * 8 + 2 * lc];
        uint2 l1 = *(const uint2*)&g_qlo[(bT + q0 + r1l) * 32 + c * 8 + 2 * lc];
        qah[c][0] = h0.x; qah[c][1] = h1.x; qah[c][2] = h0.y; qah[c][3] = h1.y;
        qal[c][0] = l0.x; qal[c][1] = l1.x; qal[c][2] = l0.y; qal[c][3] = l1.y;
    }

    float o[8][4];
    float mrow[2] = { -1e30f, -1e30f };
    float lrow[2] = { 0.f, 0.f };
#pragma unroll
    for (int nt = 0; nt < 8; nt++)
#pragma unroll
        for (int i = 0; i < 4; i++) o[nt][i] = 0.f;

    const int n_iter = 2 * qt + 2;

    // fill macro body: warp -> array arr, rows half*32..+31; 256 chunks of 16B per warp
#define FILL_TILE(stage, s0v)                                                        \
    {                                                                                \
        uint32_t base = dsmA + ((stage) * STG_W + arr * ARR_W) * 4;                  \
        _Pragma("unroll")                                                            \
        for (int i = 0; i < 8; i++) {                                                \
            int c = lane + i * 32;                                                   \
            int row = half * 32 + (c >> 3), ch = c & 7;                              \
            if (arr == 0)                                                            \
                CP16(base + row * 160 + ch * 16,                                     \
                     g_khi + (bT + (s0v) + row) * 32 + ch * 4);                      \
            else if (arr == 1)                                                       \
                CP16(base + row * 160 + ch * 16,                                     \
                     g_klo + (bT + (s0v) + row) * 32 + ch * 4);                      \
            else if (arr == 2)                                                       \
                CP16(base + row * 160 + ch * 16,                                     \
                     g_vhiT + (size_t)(b * Hn + row) * Tn + (s0v) + ch * 8);         \
            else                                                                     \
                CP16(base + row * 160 + ch * 16,                                     \
                     g_vloT + (size_t)(b * Hn + row) * Tn + (s0v) + ch * 8);         \
        }                                                                            \
        CP_COMMIT();                                                                 \
    }

    // prefetch tile 0 into stage 0
    FILL_TILE(0, 0);

    for (int st = 0; st < n_iter; st++) {
        const int s0 = st * 64;
        const int buf = st & 1;
        const uint32_t* Kh = dsm + buf * STG_W;
        const uint32_t* Kl = Kh + ARR_W;
        const uint32_t* Vh = Kl + ARR_W;
        const uint32_t* Vl = Vh + ARR_W;

        // issue next tile's fill into the other stage, then wait for THIS tile only
        if (st + 1 < n_iter) {
            FILL_TILE(buf ^ 1, s0 + 64);
            CP_WAIT1();
        } else {
            CP_WAIT0();
        }
        __syncthreads();

        // ---- S = Q K^T ----
        float sacc[8][4];
#pragma unroll
        for (int nt = 0; nt < 8; nt++)
#pragma unroll
            for (int i = 0; i < 4; i++) sacc[nt][i] = 0.f;

#pragma unroll
        for (int c = 0; c < 4; c++) {
#pragma unroll
            for (int nt = 0; nt < 8; nt++) {
                uint2 bh = *(const uint2*)&Kh[(nt * 8 + lr) * 40 + c * 8 + 2 * lc];
                uint2 bl = *(const uint2*)&Kl[(nt * 8 + lr) * 40 + c * 8 + 2 * lc];
                mmab(sacc[nt], qah[c][0], qah[c][1], qah[c][2], qah[c][3], bh.x, bh.y);
                mmab(sacc[nt], qah[c][0], qah[c][1], qah[c][2], qah[c][3], bl.x, bl.y);
                mmab(sacc[nt], qal[c][0], qal[c][1], qal[c][2], qal[c][3], bh.x, bh.y);
            }
        }

        // ---- causal mask (tiles overlapping the diagonal) ----
        if (st >= 2 * qt) {
            int r0g = q0 + r0l, r1g = q0 + r1l;
#pragma unroll
            for (int nt = 0; nt < 8; nt++) {
                int cg = s0 + nt * 8 + 2 * lc;
                if (cg > r0g)     sacc[nt][0] = -1e30f;
                if (cg + 1 > r0g) sacc[nt][1] = -1e30f;
                if (cg > r1g)     sacc[nt][2] = -1e30f;
                if (cg + 1 > r1g) sacc[nt][3] = -1e30f;
            }
        }

        // ---- online softmax ----
        float mx0 = -1e30f, mx1 = -1e30f;
#pragma unroll
        for (int nt = 0; nt < 8; nt++) {
            mx0 = fmaxf(mx0, fmaxf(sacc[nt][0], sacc[nt][1]));
            mx1 = fmaxf(mx1, fmaxf(sacc[nt][2], sacc[nt][3]));
        }
        mx0 = fmaxf(mx0, __shfl_xor_sync(0xffffffffu, mx0, 1));
        mx0 = fmaxf(mx0, __shfl_xor_sync(0xffffffffu, mx0, 2));
        mx1 = fmaxf(mx1, __shfl_xor_sync(0xffffffffu, mx1, 1));
        mx1 = fmaxf(mx1, __shfl_xor_sync(0xffffffffu, mx1, 2));

        float mn0 = fmaxf(mrow[0], mx0), mn1 = fmaxf(mrow[1], mx1);
        float f0 = __expf(mrow[0] - mn0), f1 = __expf(mrow[1] - mn1);
        mrow[0] = mn0; mrow[1] = mn1;

        float sum0 = 0.f, sum1 = 0.f;
#pragma unroll
        for (int nt = 0; nt < 8; nt++) {
            sacc[nt][0] = __expf(sacc[nt][0] - mn0);
            sacc[nt][1] = __expf(sacc[nt][1] - mn0);
            sacc[nt][2] = __expf(sacc[nt][2] - mn1);
            sacc[nt][3] = __expf(sacc[nt][3] - mn1);
            sum0 += sacc[nt][0] + sacc[nt][1];
            sum1 += sacc[nt][2] + sacc[nt][3];
        }
        sum0 += __shfl_xor_sync(0xffffffffu, sum0, 1);
        sum0 += __shfl_xor_sync(0xffffffffu, sum0, 2);
        sum1 += __shfl_xor_sync(0xffffffffu, sum1, 1);
        sum1 += __shfl_xor_sync(0xffffffffu, sum1, 2);
        lrow[0] = lrow[0] * f0 + sum0;
        lrow[1] = lrow[1] * f1 + sum1;

#pragma unroll
        for (int nt = 0; nt < 8; nt++) {
            o[nt][0] *= f0; o[nt][1] *= f0;
            o[nt][2] *= f1; o[nt][3] *= f1;
        }

        // ---- O += P V, P taken directly from sacc registers (FA2 layout identity) ----
#pragma unroll
        for (int c = 0; c < 4; c++) {
            uint32_t ah[4], al[4];
            spb2(sacc[2 * c][0],     sacc[2 * c][1],     ah[0], al[0]);
            spb2(sacc[2 * c][2],     sacc[2 * c][3],     ah[1], al[1]);
            spb2(sacc[2 * c + 1][0], sacc[2 * c + 1][1], ah[2], al[2]);
            spb2(sacc[2 * c + 1][2], sacc[2 * c + 1][3], ah[3], al[3]);
#pragma unroll
            for (int nt = 0; nt < 8; nt++) {
                uint2 vh = *(const uint2*)&Vh[(nt * 8 + lr) * 40 + c * 8 + 2 * lc];
                uint2 vl = *(const uint2*)&Vl[(nt * 8 + lr) * 40 + c * 8 + 2 * lc];
                mmab(o[nt], ah[0], ah[1], ah[2], ah[3], vh.x, vh.y);
                mmab(o[nt], ah[0], ah[1], ah[2], ah[3], vl.x, vl.y);
                mmab(o[nt], al[0], al[1], al[2], al[3], vh.x, vh.y);
            }
        }

        __syncthreads();  // all reads of this stage done before it is refilled
    }

    float inv0 = 1.0f / lrow[0], inv1 = 1.0f / lrow[1];
#pragma unroll
    for (int nt = 0; nt < 8; nt++) {
        int col = nt * 8 + 2 * lc;
        *(float2*)&out[(bT + q0 + r0l) * Hn + col] =
            make_float2(o[nt][0] * inv0, o[nt][1] * inv0);
        *(float2*)&out[(bT + q0 + r1l) * Hn + col] =
            make_float2(o[nt][2] * inv1, o[nt][3] * inv1);
    }
}

// ================= launch =================
extern "C" void kernel_launch(void* const* d_in, const int* in_sizes, int n_in,
                              void* d_out, int out_size)
{
    const float* x  = (const float*)d_in[0];
    const float* wq = (const float*)d_in[1];
    const float* wk = (const float*)d_in[2];
    const float* wv = (const float*)d_in[3];
    float* out = (float*)d_out;

    wsplit_kernel<<<dim3(32, 3), 256>>>(wq, wk, wv);
    qkv_kernel<<<dim3((Bn * Tn) / 128, 3), 128>>>(x);

    const int attn_smem = 2 * STG_W * 4;  // 81920 B
    cudaFuncSetAttribute(attn_kernel, cudaFuncAttributeMaxDynamicSharedMemorySize, attn_smem);
    attn_kernel<<<256, 256, attn_smem>>>(out);
}

// round 12
// speedup vs baseline: 2.1543x; 1.0749x over previous
#include <cuda_runtime.h>
#include <cstdint>

#define Bn 16
#define Tn 2048
#define Cn 1024
#define Hn 64

// ---------------- global scratch (pre-split bf16 operands) ----------------
__device__ uint32_t g_qhi[Bn * Tn * 32];   // Q scaled, bf16-pair words [t][kslot(h/2)]
__device__ uint32_t g_qlo[Bn * Tn * 32];
__device__ uint32_t g_khi[Bn * Tn * 32];   // K words [t][kslot(h/2)]
__device__ uint32_t g_klo[Bn * Tn * 32];
__device__ unsigned short g_vhiT[Bn * Hn * Tn];  // V^T bf16 [b][h][eperm(t)]
__device__ unsigned short g_vloT[Bn * Hn * Tn];
__device__ uint32_t g_whi[3 * 32 * 64 * 16];     // W words [which][kt][n][kslot(k/2)]
__device__ uint32_t g_wlo[3 * 32 * 64 * 16];

// ---------------- helpers ----------------
__device__ __forceinline__ unsigned short b16(float x) {
    unsigned short h;
    asm("cvt.rn.bf16.f32 %0, %1;" : "=h"(h) : "f"(x));
    return h;
}
__device__ __forceinline__ float fb16(unsigned short h) {
    return __uint_as_float((uint32_t)h << 16);
}
__device__ __forceinline__ uint32_t pkb(unsigned short lo, unsigned short hi) {
    uint32_t r;
    asm("mov.b32 %0, {%1, %2};" : "=r"(r) : "h"(lo), "h"(hi));
    return r;
}
// split pair (x0 = k-even, x1 = k-odd) into hi-word and lo-word
__device__ __forceinline__ void spb2(float x0, float x1, uint32_t& hw, uint32_t& lw) {
    unsigned short h0 = b16(x0), h1 = b16(x1);
    unsigned short l0 = b16(x0 - fb16(h0)), l1 = b16(x1 - fb16(h1));
    hw = pkb(h0, h1);
    lw = pkb(l0, l1);
}
// bf16 m16n8k16 mma, fp32 accum
__device__ __forceinline__ void mmab(float c[4],
                                     uint32_t a0, uint32_t a1, uint32_t a2, uint32_t a3,
                                     uint32_t b0, uint32_t b1) {
    asm volatile(
        "mma.sync.aligned.m16n8k16.row.col.f32.bf16.bf16.f32 "
        "{%0,%1,%2,%3}, {%4,%5,%6,%7}, {%8,%9}, {%0,%1,%2,%3};"
        : "+f"(c[0]), "+f"(c[1]), "+f"(c[2]), "+f"(c[3])
        : "r"(a0), "r"(a1), "r"(a2), "r"(a3), "r"(b0), "r"(b1));
}
// word interleave within 8-groups: (w, w+4) adjacent
__device__ __forceinline__ int kslot(int w) {
    return (w & ~7) + 2 * (w & 3) + ((w >> 2) & 1);
}
// element permutation for V^T rows so contiguous copy yields kslot word order
__device__ __forceinline__ int eperm(int t) {
    int w = (t >> 1) & 7;
    int sl = 2 * (w & 3) + ((w >> 2) & 1);
    return (t & ~15) + sl * 2 + (t & 1);
}
__device__ __forceinline__ uint32_t smem_u32(const void* p) {
    uint32_t a;
    asm("{ .reg .u64 t; cvta.to.shared.u64 t, %1; cvt.u32.u64 %0, t; }" : "=r"(a) : "l"(p));
    return a;
}
#define CP16(dst, src) \
    asm volatile("cp.async.cg.shared.global [%0], [%1], 16;" :: "r"(dst), "l"(src))
#define CP_COMMIT() asm volatile("cp.async.commit_group;" ::: "memory")
#define CP_WAIT0()  asm volatile("cp.async.wait_group 0;" ::: "memory")
#define CP_WAIT1()  asm volatile("cp.async.wait_group 1;" ::: "memory")

// ================= Kernel 0: W split -> bf16 words =================
__global__ void wsplit_kernel(const float* __restrict__ wq,
                              const float* __restrict__ wk,
                              const float* __restrict__ wv) {
    const int which = blockIdx.y, kt = blockIdx.x;
    const float* w = (which == 0) ? wq : (which == 1) ? wk : wv;
    const int tid = threadIdx.x;
#pragma unroll
    for (int i = 0; i < 4; i++) {
        int e = tid + i * 256;        // 0..1023 words
        int n = e & 63, wp = e >> 6;  // wp 0..15
        float x0 = w[(size_t)(kt * 32 + 2 * wp) * Hn + n];
        float x1 = w[(size_t)(kt * 32 + 2 * wp + 1) * Hn + n];
        uint32_t hw, lw;
        spb2(x0, x1, hw, lw);
        int dst = ((which * 32 + kt) * 64 + n) * 16 + kslot(wp);
        g_whi[dst] = hw;
        g_wlo[dst] = lw;
    }
}

// ================= Kernel 1: QKV projection (2-stage K-chunk pipeline) =================
// grid (256, 3), block 128 (4 warps, m32 x n64). M_TILE=128, K chunks of 32.
// Dynamic SMEM: 2 stages x (As 20480B + Bh 6144B + Bl 6144B) = 65536 B.
#define QSTG_B 32768          // bytes per stage
#define QAS_W  5120           // As floats per stage (128*40)
#define QBH_OFF 20480         // byte offset of Bh within stage
#define QBL_OFF 26624         // byte offset of Bl within stage
__global__ __launch_bounds__(128) void qkv_kernel(const float* __restrict__ x)
{
    extern __shared__ __align__(16) uint32_t qdsm[];

    const int which = blockIdx.y;
    const int m0 = blockIdx.x * 128;
    const int tid = threadIdx.x;
    const int wid = tid >> 5, lane = tid & 31;
    const int lr = lane >> 2, lc = lane & 3;

    const uint32_t dsmA = smem_u32(qdsm);

    float acc[2][8][4];
#pragma unroll
    for (int mt = 0; mt < 2; mt++)
#pragma unroll
        for (int nt = 0; nt < 8; nt++)
#pragma unroll
            for (int i = 0; i < 4; i++) acc[mt][nt][i] = 0.f;

    // fill one K-chunk into a stage: A 1024 chunks + B 512 chunks, 128 threads
#define FILL_QKV(stage, ktv)                                                         \
    {                                                                                \
        uint32_t sb = dsmA + (stage) * QSTG_B;                                       \
        _Pragma("unroll")                                                            \
        for (int l = 0; l < 8; l++) {                                                \
            int idx = tid + l * 128;                                                 \
            int row = idx >> 3, ch = idx & 7;                                        \
            CP16(sb + row * 160 + ch * 16,                                           \
                 x + (size_t)(m0 + row) * Cn + (ktv) * 32 + ch * 4);                 \
        }                                                                            \
        const size_t tb = (size_t)(which * 32 + (ktv)) * 1024;                       \
        _Pragma("unroll")                                                            \
        for (int l = 0; l < 4; l++) {                                                \
            int idx = tid + l * 128;                                                 \
            int sel = idx >> 8;                                                      \
            int r = idx & 255;                                                       \
            int n = r >> 2, ch = r & 3;                                              \
            uint32_t dst = sb + (sel ? QBL_OFF : QBH_OFF) + n * 96 + ch * 16;        \
            const uint32_t* src = (sel ? g_wlo : g_whi) + tb + n * 16 + ch * 4;      \
            CP16(dst, src);                                                          \
        }                                                                            \
        CP_COMMIT();                                                                 \
    }

    FILL_QKV(0, 0);   // prefetch chunk 0

    for (int kt = 0; kt < Cn / 32; kt++) {
        const int buf = kt & 1;
        const float* As = (const float*)(qdsm + buf * (QSTG_B / 4));
        const uint32_t* Bh = qdsm + buf * (QSTG_B / 4) + QBH_OFF / 4;
        const uint32_t* Bl = qdsm + buf * (QSTG_B / 4) + QBL_OFF / 4;

        if (kt + 1 < Cn / 32) {
            FILL_QKV(buf ^ 1, kt + 1);
            CP_WAIT1();
        } else {
            CP_WAIT0();
        }
        __syncthreads();

#pragma unroll
        for (int c = 0; c < 2; c++) {         // two k16 chunks
            uint32_t ah[2][4], al[2][4];
#pragma unroll
            for (int mt = 0; mt < 2; mt++) {
                int rb = wid * 32 + mt * 16 + lr;
                float2 p0 = *(const float2*)&As[rb * 40 + c * 16 + 2 * lc];
                float2 p1 = *(const float2*)&As[(rb + 8) * 40 + c * 16 + 2 * lc];
                float2 p2 = *(const float2*)&As[rb * 40 + c * 16 + 8 + 2 * lc];
                float2 p3 = *(const float2*)&As[(rb + 8) * 40 + c * 16 + 8 + 2 * lc];
                spb2(p0.x, p0.y, ah[mt][0], al[mt][0]);
                spb2(p1.x, p1.y, ah[mt][1], al[mt][1]);
                spb2(p2.x, p2.y, ah[mt][2], al[mt][2]);
                spb2(p3.x, p3.y, ah[mt][3], al[mt][3]);
            }
#pragma unroll
            for (int nt = 0; nt < 8; nt++) {
                uint2 bh = *(const uint2*)&Bh[(nt * 8 + lr) * 24 + c * 8 + 2 * lc];
                uint2 bl = *(const uint2*)&Bl[(nt * 8 + lr) * 24 + c * 8 + 2 * lc];
#pragma unroll
                for (int mt = 0; mt < 2; mt++) {
                    mmab(acc[mt][nt], ah[mt][0], ah[mt][1], ah[mt][2], ah[mt][3], bh.x, bh.y);
                    mmab(acc[mt][nt], ah[mt][0], ah[mt][1], ah[mt][2], ah[mt][3], bl.x, bl.y);
                    mmab(acc[mt][nt], al[mt][0], al[mt][1], al[mt][2], al[mt][3], bh.x, bh.y);
                }
            }
        }
        __syncthreads();  // stage reads done before it is refilled
    }

    // Epilogue: pre-split / pre-pack by output kind
#pragma unroll
    for (int mt = 0; mt < 2; mt++)
#pragma unroll
        for (int rr = 0; rr < 2; rr++) {
            int row = m0 + wid * 32 + mt * 16 + rr * 8 + lr;
#pragma unroll
            for (int nt = 0; nt < 8; nt++) {
                float v0 = acc[mt][nt][rr * 2 + 0];
                float v1 = acc[mt][nt][rr * 2 + 1];
                int col0 = nt * 8 + 2 * lc;
                int sl = kslot(nt * 4 + lc);
                if (which == 0) {
                    uint32_t hw, lw;
                    spb2(v0 * 0.125f, v1 * 0.125f, hw, lw);
                    g_qhi[(size_t)row * 32 + sl] = hw;
                    g_qlo[(size_t)row * 32 + sl] = lw;
                } else if (which == 1) {
                    uint32_t hw, lw;
                    spb2(v0, v1, hw, lw);
                    g_khi[(size_t)row * 32 + sl] = hw;
                    g_klo[(size_t)row * 32 + sl] = lw;
                } else {
                    int bb = row >> 11, t = row & 2047;
                    int ep = eperm(t);
                    unsigned short h0 = b16(v0);
                    unsigned short l0 = b16(v0 - fb16(h0));
                    unsigned short h1 = b16(v1);
                    unsigned short l1 = b16(v1 - fb16(h1));
                    g_vhiT[(size_t)(bb * Hn + col0) * Tn + ep] = h0;
                    g_vloT[(size_t)(bb * Hn + col0) * Tn + ep] = l0;
                    g_vhiT[(size_t)(bb * Hn + col0 + 1) * Tn + ep] = h1;
                    g_vloT[(size_t)(bb * Hn + col0 + 1) * Tn + ep] = l1;
                }
            }
        }
}

// ================= Kernel 2: flash attention (register P + 2-stage K/V pipeline, R11) =================
// grid 256 (heavy-first), block 256 (8 warps, each m16 x n64). Q_TILE=128, KV_TILE=64.
// Dynamic SMEM: 2 stages x 4 arrays x 64 x 40 words = 81920 B.
#define STG_W 10240   // words per stage
#define ARR_W 2560    // words per array (64 * 40)
__global__ __launch_bounds__(256) void attn_kernel(float* __restrict__ out)
{
    extern __shared__ __align__(16) uint32_t dsm[];

    const int qt = 15 - (blockIdx.x >> 4);
    const int b  = blockIdx.x & 15;
    const int q0 = qt * 128;
    const size_t bT = (size_t)b * Tn;
    const int tid = threadIdx.x;
    const int wid = tid >> 5, lane = tid & 31;
    const int lr = lane >> 2, lc = lane & 3;
    const int r0l = wid * 16 + lr, r1l = r0l + 8;    // local q rows (0..127)

    const uint32_t dsmA = smem_u32(dsm);
    const int arr = wid >> 1, half = wid & 1;        // fill ownership

    // Q fragments: pre-split, pre-packed words straight from global
    uint32_t qah[4][4], qal[4][4];
#pragma unroll
    for (int c = 0; c < 4; c++) {
        uint2 h0 = *(const uint2*)&g_qhi[(bT + q0 + r0l) * 32 + c * 8 + 2 * lc];
        uint2 h1 = *(const uint2*)&g_qhi[(bT + q0 + r1l) * 32 + c * 8 + 2 * lc];
        uint2 l0 = *(const uint2*)&g_qlo[(bT + q0 + r0l) * 32 + c * 8 + 2 * lc];
        uint2 l1 = *(const uint2*)&g_qlo[(bT + q0 + r1l) * 32 + c * 8 + 2 * lc];
        qah[c][0] = h0.x; qah[c][1] = h1.x; qah[c][2] = h0.y; qah[c][3] = h1.y;
        qal[c][0] = l0.x; qal[c][1] = l1.x; qal[c][2] = l0.y; qal[c][3] = l1.y;
    }

    float o[8][4];
    float mrow[2] = { -1e30f, -1e30f };
    float lrow[2] = { 0.f, 0.f };
#pragma unroll
    for (int nt = 0; nt < 8; nt++)
#pragma unroll
        for (int i = 0; i < 4; i++) o[nt][i] = 0.f;

    const int n_iter = 2 * qt + 2;

    // fill macro body: warp -> array arr, rows half*32..+31; 256 chunks of 16B per warp
#define FILL_TILE(stage, s0v)                                                        \
    {                                                                                \
        uint32_t base = dsmA + ((stage) * STG_W + arr * ARR_W) * 4;                  \
        _Pragma("unroll")                                                            \
        for (int i = 0; i < 8; i++) {                                                \
            int c = lane + i * 32;                                                   \
            int row = half * 32 + (c >> 3), ch = c & 7;                              \
            if (arr == 0)                                                            \
                CP16(base + row * 160 + ch * 16,                                     \
                     g_khi + (bT + (s0v) + row) * 32 + ch * 4);                      \
            else if (arr == 1)                                                       \
                CP16(base + row * 160 + ch * 16,                                     \
                     g_klo + (bT + (s0v) + row) * 32 + ch * 4);                      \
            else if (arr == 2)                                                       \
                CP16(base + row * 160 + ch * 16,                                     \
                     g_vhiT + (size_t)(b * Hn + row) * Tn + (s0v) + ch * 8);         \
            else                                                                     \
                CP16(base + row * 160 + ch * 16,                                     \
                     g_vloT + (size_t)(b * Hn + row) * Tn + (s0v) + ch * 8);         \
        }                                                                            \
        CP_COMMIT();                                                                 \
    }

    // prefetch tile 0 into stage 0
    FILL_TILE(0, 0);

    for (int st = 0; st < n_iter; st++) {
        const int s0 = st * 64;
        const int buf = st & 1;
        const uint32_t* Kh = dsm + buf * STG_W;
        const uint32_t* Kl = Kh + ARR_W;
        const uint32_t* Vh = Kl + ARR_W;
        const uint32_t* Vl = Vh + ARR_W;

        // issue next tile's fill into the other stage, then wait for THIS tile only
        if (st + 1 < n_iter) {
            FILL_TILE(buf ^ 1, s0 + 64);
            CP_WAIT1();
        } else {
            CP_WAIT0();
        }
        __syncthreads();

        // ---- S = Q K^T ----
        float sacc[8][4];
#pragma unroll
        for (int nt = 0; nt < 8; nt++)
#pragma unroll
            for (int i = 0; i < 4; i++) sacc[nt][i] = 0.f;

#pragma unroll
        for (int c = 0; c < 4; c++) {
#pragma unroll
            for (int nt = 0; nt < 8; nt++) {
                uint2 bh = *(const uint2*)&Kh[(nt * 8 + lr) * 40 + c * 8 + 2 * lc];
                uint2 bl = *(const uint2*)&Kl[(nt * 8 + lr) * 40 + c * 8 + 2 * lc];
                mmab(sacc[nt], qah[c][0], qah[c][1], qah[c][2], qah[c][3], bh.x, bh.y);
                mmab(sacc[nt], qah[c][0], qah[c][1], qah[c][2], qah[c][3], bl.x, bl.y);
                mmab(sacc[nt], qal[c][0], qal[c][1], qal[c][2], qal[c][3], bh.x, bh.y);
            }
        }

        // ---- causal mask (tiles overlapping the diagonal) ----
        if (st >= 2 * qt) {
            int r0g = q0 + r0l, r1g = q0 + r1l;
#pragma unroll
            for (int nt = 0; nt < 8; nt++) {
                int cg = s0 + nt * 8 + 2 * lc;
                if (cg > r0g)     sacc[nt][0] = -1e30f;
                if (cg + 1 > r0g) sacc[nt][1] = -1e30f;
                if (cg > r1g)     sacc[nt][2] = -1e30f;
                if (cg + 1 > r1g) sacc[nt][3] = -1e30f;
            }
        }

        // ---- online softmax ----
        float mx0 = -1e30f, mx1 = -1e30f;
#pragma unroll
        for (int nt = 0; nt < 8; nt++) {
            mx0 = fmaxf(mx0, fmaxf(sacc[nt][0], sacc[nt][1]));
            mx1 = fmaxf(mx1, fmaxf(sacc[nt][2], sacc[nt][3]));
        }
        mx0 = fmaxf(mx0, __shfl_xor_sync(0xffffffffu, mx0, 1));
        mx0 = fmaxf(mx0, __shfl_xor_sync(0xffffffffu, mx0, 2));
        mx1 = fmaxf(mx1, __shfl_xor_sync(0xffffffffu, mx1, 1));
        mx1 = fmaxf(mx1, __shfl_xor_sync(0xffffffffu, mx1, 2));

        float mn0 = fmaxf(mrow[0], mx0), mn1 = fmaxf(mrow[1], mx1);
        float f0 = __expf(mrow[0] - mn0), f1 = __expf(mrow[1] - mn1);
        mrow[0] = mn0; mrow[1] = mn1;

        float sum0 = 0.f, sum1 = 0.f;
#pragma unroll
        for (int nt = 0; nt < 8; nt++) {
            sacc[nt][0] = __expf(sacc[nt][0] - mn0);
            sacc[nt][1] = __expf(sacc[nt][1] - mn0);
            sacc[nt][2] = __expf(sacc[nt][2] - mn1);
            sacc[nt][3] = __expf(sacc[nt][3] - mn1);
            sum0 += sacc[nt][0] + sacc[nt][1];
            sum1 += sacc[nt][2] + sacc[nt][3];
        }
        sum0 += __shfl_xor_sync(0xffffffffu, sum0, 1);
        sum0 += __shfl_xor_sync(0xffffffffu, sum0, 2);
        sum1 += __shfl_xor_sync(0xffffffffu, sum1, 1);
        sum1 += __shfl_xor_sync(0xffffffffu, sum1, 2);
        lrow[0] = lrow[0] * f0 + sum0;
        lrow[1] = lrow[1] * f1 + sum1;

#pragma unroll
        for (int nt = 0; nt < 8; nt++) {
            o[nt][0] *= f0; o[nt][1] *= f0;
            o[nt][2] *= f1; o[nt][3] *= f1;
        }

        // ---- O += P V, P taken directly from sacc registers (FA2 layout identity) ----
#pragma unroll
        for (int c = 0; c < 4; c++) {
            uint32_t ah[4], al[4];
            spb2(sacc[2 * c][0],     sacc[2 * c][1],     ah[0], al[0]);
            spb2(sacc[2 * c][2],     sacc[2 * c][3],     ah[1], al[1]);
            spb2(sacc[2 * c + 1][0], sacc[2 * c + 1][1], ah[2], al[2]);
            spb2(sacc[2 * c + 1][2], sacc[2 * c + 1][3], ah[3], al[3]);
#pragma unroll
            for (int nt = 0; nt < 8; nt++) {
                uint2 vh = *(const uint2*)&Vh[(nt * 8 + lr) * 40 + c * 8 + 2 * lc];
                uint2 vl = *(const uint2*)&Vl[(nt * 8 + lr) * 40 + c * 8 + 2 * lc];
                mmab(o[nt], ah[0], ah[1], ah[2], ah[3], vh.x, vh.y);
                mmab(o[nt], ah[0], ah[1], ah[2], ah[3], vl.x, vl.y);
                mmab(o[nt], al[0], al[1], al[2], al[3], vh.x, vh.y);
            }
        }

        __syncthreads();  // all reads of this stage done before it is refilled
    }

    float inv0 = 1.0f / lrow[0], inv1 = 1.0f / lrow[1];
#pragma unroll
    for (int nt = 0; nt < 8; nt++) {
        int col = nt * 8 + 2 * lc;
        *(float2*)&out[(bT + q0 + r0l) * Hn + col] =
            make_float2(o[nt][0] * inv0, o[nt][1] * inv0);
        *(float2*)&out[(bT + q0 + r1l) * Hn + col] =
            make_float2(o[nt][2] * inv1, o[nt][3] * inv1);
    }
}

// ================= launch =================
extern "C" void kernel_launch(void* const* d_in, const int* in_sizes, int n_in,
                              void* d_out, int out_size)
{
    const float* x  = (const float*)d_in[0];
    const float* wq = (const float*)d_in[1];
    const float* wk = (const float*)d_in[2];
    const float* wv = (const float*)d_in[3];
    float* out = (float*)d_out;

    wsplit_kernel<<<dim3(32, 3), 256>>>(wq, wk, wv);

    const int qkv_smem = 2 * QSTG_B;  // 65536 B
    cudaFuncSetAttribute(qkv_kernel, cudaFuncAttributeMaxDynamicSharedMemorySize, qkv_smem);
    qkv_kernel<<<dim3((Bn * Tn) / 128, 3), 128, qkv_smem>>>(x);

    const int attn_smem = 2 * STG_W * 4;  // 81920 B
    cudaFuncSetAttribute(attn_kernel, cudaFuncAttributeMaxDynamicSharedMemorySize, attn_smem);
    attn_kernel<<<256, 256, attn_smem>>>(out);
}

// round 13
// speedup vs baseline: 2.7800x; 1.2904x over previous
#include <cuda_runtime.h>
#include <cstdint>

#define Bn 16
#define Tn 2048
#define Cn 1024
#define Hn 64

// ---------------- global scratch (fp16 operands) ----------------
__device__ uint32_t g_qhi[Bn * Tn * 32];   // Q scaled, fp16-pair words [t][kslot(h/2)], hi/lo split
__device__ uint32_t g_qlo[Bn * Tn * 32];
__device__ uint32_t g_kf[Bn * Tn * 32];    // K single-rounded fp16 words [t][kslot(h/2)]
__device__ unsigned short g_vfT[Bn * Hn * Tn];  // V^T single-rounded fp16 [b][h][eperm(t)]
__device__ uint32_t g_whf[3 * 32 * 64 * 16];    // W hi words [which][kt][n][kslot(k/2)]
__device__ uint32_t g_wlf[3 * 32 * 64 * 16];    // W lo words

// ---------------- helpers ----------------
__device__ __forceinline__ unsigned short f16(float x) {
    unsigned short h;
    asm("cvt.rn.f16.f32 %0, %1;" : "=h"(h) : "f"(x));
    return h;
}
__device__ __forceinline__ float ff16(unsigned short h) {
    float f;
    asm("cvt.f32.f16 %0, %1;" : "=f"(f) : "h"(h));
    return f;
}
__device__ __forceinline__ uint32_t pkb(unsigned short lo, unsigned short hi) {
    uint32_t r;
    asm("mov.b32 %0, {%1, %2};" : "=r"(r) : "h"(lo), "h"(hi));
    return r;
}
// split pair (x0 = k-even, x1 = k-odd) into fp16 hi-word and lo-word
__device__ __forceinline__ void sph2(float x0, float x1, uint32_t& hw, uint32_t& lw) {
    unsigned short h0 = f16(x0), h1 = f16(x1);
    unsigned short l0 = f16(x0 - ff16(h0)), l1 = f16(x1 - ff16(h1));
    hw = pkb(h0, h1);
    lw = pkb(l0, l1);
}
// single-round pair to one fp16 word
__device__ __forceinline__ uint32_t rph2(float x0, float x1) {
    return pkb(f16(x0), f16(x1));
}
// fp16 m16n8k16 mma, fp32 accum
__device__ __forceinline__ void mmah(float c[4],
                                     uint32_t a0, uint32_t a1, uint32_t a2, uint32_t a3,
                                     uint32_t b0, uint32_t b1) {
    asm volatile(
        "mma.sync.aligned.m16n8k16.row.col.f32.f16.f16.f32 "
        "{%0,%1,%2,%3}, {%4,%5,%6,%7}, {%8,%9}, {%0,%1,%2,%3};"
        : "+f"(c[0]), "+f"(c[1]), "+f"(c[2]), "+f"(c[3])
        : "r"(a0), "r"(a1), "r"(a2), "r"(a3), "r"(b0), "r"(b1));
}
// word interleave within 8-groups: (w, w+4) adjacent
__device__ __forceinline__ int kslot(int w) {
    return (w & ~7) + 2 * (w & 3) + ((w >> 2) & 1);
}
// element permutation for V^T rows so contiguous copy yields kslot word order
__device__ __forceinline__ int eperm(int t) {
    int w = (t >> 1) & 7;
    int sl = 2 * (w & 3) + ((w >> 2) & 1);
    return (t & ~15) + sl * 2 + (t & 1);
}
__device__ __forceinline__ uint32_t smem_u32(const void* p) {
    uint32_t a;
    asm("{ .reg .u64 t; cvta.to.shared.u64 t, %1; cvt.u32.u64 %0, t; }" : "=r"(a) : "l"(p));
    return a;
}
#define CP16(dst, src) \
    asm volatile("cp.async.cg.shared.global [%0], [%1], 16;" :: "r"(dst), "l"(src))
#define CP_COMMIT() asm volatile("cp.async.commit_group;" ::: "memory")
#define CP_WAIT0()  asm volatile("cp.async.wait_group 0;" ::: "memory")
#define CP_WAIT1()  asm volatile("cp.async.wait_group 1;" ::: "memory")

// ================= Kernel 0: W split -> fp16 hi/lo words =================
__global__ void wsplit_kernel(const float* __restrict__ wq,
                              const float* __restrict__ wk,
                              const float* __restrict__ wv) {
    const int which = blockIdx.y, kt = blockIdx.x;
    const float* w = (which == 0) ? wq : (which == 1) ? wk : wv;
    const int tid = threadIdx.x;
#pragma unroll
    for (int i = 0; i < 4; i++) {
        int e = tid + i * 256;        // 0..1023 words
        int n = e & 63, wp = e >> 6;  // wp 0..15
        float x0 = w[(size_t)(kt * 32 + 2 * wp) * Hn + n];
        float x1 = w[(size_t)(kt * 32 + 2 * wp + 1) * Hn + n];
        uint32_t hw, lw;
        sph2(x0, x1, hw, lw);
        int dst = ((which * 32 + kt) * 64 + n) * 16 + kslot(wp);
        g_whf[dst] = hw;
        g_wlf[dst] = lw;
    }
}

// ================= Kernel 1: QKV projection (2-stage pipeline, fp16 2-term) =================
// grid (256, 3), block 128 (4 warps, m32 x n64). M_TILE=128, K chunks of 32.
// A = x single-rounded fp16 (in regs from SMEM fp32); B = W hi/lo (precomputed).
// Dynamic SMEM: 2 stages x (As 20480B + Bh 6144B + Bl 6144B) = 65536 B.
#define QSTG_B 32768
#define QBH_OFF 20480
#define QBL_OFF 26624
__global__ __launch_bounds__(128) void qkv_kernel(const float* __restrict__ x)
{
    extern __shared__ __align__(16) uint32_t qdsm[];

    const int which = blockIdx.y;
    const int m0 = blockIdx.x * 128;
    const int tid = threadIdx.x;
    const int wid = tid >> 5, lane = tid & 31;
    const int lr = lane >> 2, lc = lane & 3;

    const uint32_t dsmA = smem_u32(qdsm);

    float acc[2][8][4];
#pragma unroll
    for (int mt = 0; mt < 2; mt++)
#pragma unroll
        for (int nt = 0; nt < 8; nt++)
#pragma unroll
            for (int i = 0; i < 4; i++) acc[mt][nt][i] = 0.f;

#define FILL_QKV(stage, ktv)                                                         \
    {                                                                                \
        uint32_t sb = dsmA + (stage) * QSTG_B;                                       \
        _Pragma("unroll")                                                            \
        for (int l = 0; l < 8; l++) {                                                \
            int idx = tid + l * 128;                                                 \
            int row = idx >> 3, ch = idx & 7;                                        \
            CP16(sb + row * 160 + ch * 16,                                           \
                 x + (size_t)(m0 + row) * Cn + (ktv) * 32 + ch * 4);                 \
        }                                                                            \
        const size_t tb = (size_t)(which * 32 + (ktv)) * 1024;                       \
        _Pragma("unroll")                                                            \
        for (int l = 0; l < 4; l++) {                                                \
            int idx = tid + l * 128;                                                 \
            int sel = idx >> 8;                                                      \
            int r = idx & 255;                                                       \
            int n = r >> 2, ch = r & 3;                                              \
            uint32_t dst = sb + (sel ? QBL_OFF : QBH_OFF) + n * 96 + ch * 16;        \
            const uint32_t* src = (sel ? g_wlf : g_whf) + tb + n * 16 + ch * 4;      \
            CP16(dst, src);                                                          \
        }                                                                            \
        CP_COMMIT();                                                                 \
    }

    FILL_QKV(0, 0);

    for (int kt = 0; kt < Cn / 32; kt++) {
        const int buf = kt & 1;
        const float* As = (const float*)(qdsm + buf * (QSTG_B / 4));
        const uint32_t* Bh = qdsm + buf * (QSTG_B / 4) + QBH_OFF / 4;
        const uint32_t* Bl = qdsm + buf * (QSTG_B / 4) + QBL_OFF / 4;

        if (kt + 1 < Cn / 32) {
            FILL_QKV(buf ^ 1, kt + 1);
            CP_WAIT1();
        } else {
            CP_WAIT0();
        }
        __syncthreads();

#pragma unroll
        for (int c = 0; c < 2; c++) {         // two k16 chunks
            uint32_t af[2][4];
#pragma unroll
            for (int mt = 0; mt < 2; mt++) {
                int rb = wid * 32 + mt * 16 + lr;
                float2 p0 = *(const float2*)&As[rb * 40 + c * 16 + 2 * lc];
                float2 p1 = *(const float2*)&As[(rb + 8) * 40 + c * 16 + 2 * lc];
                float2 p2 = *(const float2*)&As[rb * 40 + c * 16 + 8 + 2 * lc];
                float2 p3 = *(const float2*)&As[(rb + 8) * 40 + c * 16 + 8 + 2 * lc];
                af[mt][0] = rph2(p0.x, p0.y);
                af[mt][1] = rph2(p1.x, p1.y);
                af[mt][2] = rph2(p2.x, p2.y);
                af[mt][3] = rph2(p3.x, p3.y);
            }
#pragma unroll
            for (int nt = 0; nt < 8; nt++) {
                uint2 bh = *(const uint2*)&Bh[(nt * 8 + lr) * 24 + c * 8 + 2 * lc];
                uint2 bl = *(const uint2*)&Bl[(nt * 8 + lr) * 24 + c * 8 + 2 * lc];
#pragma unroll
                for (int mt = 0; mt < 2; mt++) {
                    mmah(acc[mt][nt], af[mt][0], af[mt][1], af[mt][2], af[mt][3], bh.x, bh.y);
                    mmah(acc[mt][nt], af[mt][0], af[mt][1], af[mt][2], af[mt][3], bl.x, bl.y);
                }
            }
        }
        __syncthreads();  // stage reads done before it is refilled
    }

    // Epilogue: pack by output kind
#pragma unroll
    for (int mt = 0; mt < 2; mt++)
#pragma unroll
        for (int rr = 0; rr < 2; rr++) {
            int row = m0 + wid * 32 + mt * 16 + rr * 8 + lr;
#pragma unroll
            for (int nt = 0; nt < 8; nt++) {
                float v0 = acc[mt][nt][rr * 2 + 0];
                float v1 = acc[mt][nt][rr * 2 + 1];
                int col0 = nt * 8 + 2 * lc;
                int sl = kslot(nt * 4 + lc);
                if (which == 0) {
                    uint32_t hw, lw;
                    sph2(v0 * 0.125f, v1 * 0.125f, hw, lw);
                    g_qhi[(size_t)row * 32 + sl] = hw;
                    g_qlo[(size_t)row * 32 + sl] = lw;
                } else if (which == 1) {
                    g_kf[(size_t)row * 32 + sl] = rph2(v0, v1);
                } else {
                    int bb = row >> 11, t = row & 2047;
                    int ep = eperm(t);
                    g_vfT[(size_t)(bb * Hn + col0) * Tn + ep] = f16(v0);
                    g_vfT[(size_t)(bb * Hn + col0 + 1) * Tn + ep] = f16(v1);
                }
            }
        }
}

// ================= Kernel 2: flash attention (register P, fp16 2-term, 2-stage K/V) =================
// grid 256 (heavy-first), block 256 (8 warps, each m16 x n64). Q_TILE=128, KV_TILE=64.
// Static SMEM: 2 stages x (Kf 2560 + Vf 2560) words = 40960 B.
#define STG_W 5120    // words per stage
#define ARR_W 2560    // words per array (64 * 40)
__global__ __launch_bounds__(256) void attn_kernel(float* __restrict__ out)
{
    __shared__ __align__(16) uint32_t dsm[2 * STG_W];

    const int qt = 15 - (blockIdx.x >> 4);
    const int b  = blockIdx.x & 15;
    const int q0 = qt * 128;
    const size_t bT = (size_t)b * Tn;
    const int tid = threadIdx.x;
    const int wid = tid >> 5, lane = tid & 31;
    const int lr = lane >> 2, lc = lane & 3;
    const int r0l = wid * 16 + lr, r1l = r0l + 8;    // local q rows (0..127)

    const uint32_t dsmA = smem_u32(dsm);
    const int arr = wid >> 2, quarter = wid & 3;     // fill ownership: 2 arrays x 4 quarters

    // Q fragments: pre-split fp16 words straight from global
    uint32_t qah[4][4], qal[4][4];
#pragma unroll
    for (int c = 0; c < 4; c++) {
        uint2 h0 = *(const uint2*)&g_qhi[(bT + q0 + r0l) * 32 + c * 8 + 2 * lc];
        uint2 h1 = *(const uint2*)&g_qhi[(bT + q0 + r1l) * 32 + c * 8 + 2 * lc];
        uint2 l0 = *(const uint2*)&g_qlo[(bT + q0 + r0l) * 32 + c * 8 + 2 * lc];
        uint2 l1 = *(const uint2*)&g_qlo[(bT + q0 + r1l) * 32 + c * 8 + 2 * lc];
        qah[c][0] = h0.x; qah[c][1] = h1.x; qah[c][2] = h0.y; qah[c][3] = h1.y;
        qal[c][0] = l0.x; qal[c][1] = l1.x; qal[c][2] = l0.y; qal[c][3] = l1.y;
    }

    float o[8][4];
    float mrow[2] = { -1e30f, -1e30f };
    float lrow[2] = { 0.f, 0.f };
#pragma unroll
    for (int nt = 0; nt < 8; nt++)
#pragma unroll
        for (int i = 0; i < 4; i++) o[nt][i] = 0.f;

    const int n_iter = 2 * qt + 2;

    // fill: warp -> array arr, rows quarter*16..+15; 16 rows x 8 chunks = 128 chunks per warp
#define FILL_TILE(stage, s0v)                                                        \
    {                                                                                \
        uint32_t base = dsmA + ((stage) * STG_W + arr * ARR_W) * 4;                  \
        _Pragma("unroll")                                                            \
        for (int i = 0; i < 4; i++) {                                                \
            int c = lane + i * 32;                                                   \
            int row = quarter * 16 + (c >> 3), ch = c & 7;                           \
            if (arr == 0)                                                            \
                CP16(base + row * 160 + ch * 16,                                     \
                     g_kf + (bT + (s0v) + row) * 32 + ch * 4);                       \
            else                                                                     \
                CP16(base + row * 160 + ch * 16,                                     \
                     g_vfT + (size_t)(b * Hn + row) * Tn + (s0v) + ch * 8);          \
        }                                                                            \
        CP_COMMIT();                                                                 \
    }

    FILL_TILE(0, 0);   // prefetch tile 0

    for (int st = 0; st < n_iter; st++) {
        const int s0 = st * 64;
        const int buf = st & 1;
        const uint32_t* Kf = dsm + buf * STG_W;
        const uint32_t* Vf = Kf + ARR_W;

        if (st + 1 < n_iter) {
            FILL_TILE(buf ^ 1, s0 + 64);
            CP_WAIT1();
        } else {
            CP_WAIT0();
        }
        __syncthreads();

        // ---- S = Q K^T (2 terms) ----
        float sacc[8][4];
#pragma unroll
        for (int nt = 0; nt < 8; nt++)
#pragma unroll
            for (int i = 0; i < 4; i++) sacc[nt][i] = 0.f;

#pragma unroll
        for (int c = 0; c < 4; c++) {
#pragma unroll
            for (int nt = 0; nt < 8; nt++) {
                uint2 bf = *(const uint2*)&Kf[(nt * 8 + lr) * 40 + c * 8 + 2 * lc];
                mmah(sacc[nt], qah[c][0], qah[c][1], qah[c][2], qah[c][3], bf.x, bf.y);
                mmah(sacc[nt], qal[c][0], qal[c][1], qal[c][2], qal[c][3], bf.x, bf.y);
            }
        }

        // ---- causal mask (tiles overlapping the diagonal) ----
        if (st >= 2 * qt) {
            int r0g = q0 + r0l, r1g = q0 + r1l;
#pragma unroll
            for (int nt = 0; nt < 8; nt++) {
                int cg = s0 + nt * 8 + 2 * lc;
                if (cg > r0g)     sacc[nt][0] = -1e30f;
                if (cg + 1 > r0g) sacc[nt][1] = -1e30f;
                if (cg > r1g)     sacc[nt][2] = -1e30f;
                if (cg + 1 > r1g) sacc[nt][3] = -1e30f;
            }
        }

        // ---- online softmax ----
        float mx0 = -1e30f, mx1 = -1e30f;
#pragma unroll
        for (int nt = 0; nt < 8; nt++) {
            mx0 = fmaxf(mx0, fmaxf(sacc[nt][0], sacc[nt][1]));
            mx1 = fmaxf(mx1, fmaxf(sacc[nt][2], sacc[nt][3]));
        }
        mx0 = fmaxf(mx0, __shfl_xor_sync(0xffffffffu, mx0, 1));
        mx0 = fmaxf(mx0, __shfl_xor_sync(0xffffffffu, mx0, 2));
        mx1 = fmaxf(mx1, __shfl_xor_sync(0xffffffffu, mx1, 1));
        mx1 = fmaxf(mx1, __shfl_xor_sync(0xffffffffu, mx1, 2));

        float mn0 = fmaxf(mrow[0], mx0), mn1 = fmaxf(mrow[1], mx1);
        float f0 = __expf(mrow[0] - mn0), f1 = __expf(mrow[1] - mn1);
        mrow[0] = mn0; mrow[1] = mn1;

        float sum0 = 0.f, sum1 = 0.f;
#pragma unroll
        for (int nt = 0; nt < 8; nt++) {
            sacc[nt][0] = __expf(sacc[nt][0] - mn0);
            sacc[nt][1] = __expf(sacc[nt][1] - mn0);
            sacc[nt][2] = __expf(sacc[nt][2] - mn1);
            sacc[nt][3] = __expf(sacc[nt][3] - mn1);
            sum0 += sacc[nt][0] + sacc[nt][1];
            sum1 += sacc[nt][2] + sacc[nt][3];
        }
        sum0 += __shfl_xor_sync(0xffffffffu, sum0, 1);
        sum0 += __shfl_xor_sync(0xffffffffu, sum0, 2);
        sum1 += __shfl_xor_sync(0xffffffffu, sum1, 1);
        sum1 += __shfl_xor_sync(0xffffffffu, sum1, 2);
        lrow[0] = lrow[0] * f0 + sum0;
        lrow[1] = lrow[1] * f1 + sum1;

#pragma unroll
        for (int nt = 0; nt < 8; nt++) {
            o[nt][0] *= f0; o[nt][1] *= f0;
            o[nt][2] *= f1; o[nt][3] *= f1;
        }

        // ---- O += P V, P split fp16 hi/lo in registers (FA2 layout identity) ----
#pragma unroll
        for (int c = 0; c < 4; c++) {
            uint32_t ph[4], pl[4];
            sph2(sacc[2 * c][0],     sacc[2 * c][1],     ph[0], pl[0]);
            sph2(sacc[2 * c][2],     sacc[2 * c][3],     ph[1], pl[1]);
            sph2(sacc[2 * c + 1][0], sacc[2 * c + 1][1], ph[2], pl[2]);
            sph2(sacc[2 * c + 1][2], sacc[2 * c + 1][3], ph[3], pl[3]);
#pragma unroll
            for (int nt = 0; nt < 8; nt++) {
                uint2 vf = *(const uint2*)&Vf[(nt * 8 + lr) * 40 + c * 8 + 2 * lc];
                mmah(o[nt], ph[0], ph[1], ph[2], ph[3], vf.x, vf.y);
                mmah(o[nt], pl[0], pl[1], pl[2], pl[3], vf.x, vf.y);
            }
        }

        __syncthreads();  // all reads of this stage done before it is refilled
    }

    float inv0 = 1.0f / lrow[0], inv1 = 1.0f / lrow[1];
#pragma unroll
    for (int nt = 0; nt < 8; nt++) {
        int col = nt * 8 + 2 * lc;
        *(float2*)&out[(bT + q0 + r0l) * Hn + col] =
            make_float2(o[nt][0] * inv0, o[nt][1] * inv0);
        *(float2*)&out[(bT + q0 + r1l) * Hn + col] =
            make_float2(o[nt][2] * inv1, o[nt][3] * inv1);
    }
}

// ================= launch =================
extern "C" void kernel_launch(void* const* d_in, const int* in_sizes, int n_in,
                              void* d_out, int out_size)
{
    const float* x  = (const float*)d_in[0];
    const float* wq = (const float*)d_in[1];
    const float* wk = (const float*)d_in[2];
    const float* wv = (const float*)d_in[3];
    float* out = (float*)d_out;

    wsplit_kernel<<<dim3(32, 3), 256>>>(wq, wk, wv);

    const int qkv_smem = 2 * QSTG_B;  // 65536 B
    cudaFuncSetAttribute(qkv_kernel, cudaFuncAttributeMaxDynamicSharedMemorySize, qkv_smem);
    qkv_kernel<<<dim3((Bn * Tn) / 128, 3), 128, qkv_smem>>>(x);

    attn_kernel<<<256, 256>>>(out);
}

// round 14
// speedup vs baseline: 3.2756x; 1.1783x over previous
#include <cuda_runtime.h>
#include <cstdint>

#define Bn 16
#define Tn 2048
#define Cn 1024
#define Hn 64

// ---------------- global scratch (fp16 operands) ----------------
__device__ uint32_t g_qhi[Bn * Tn * 32];   // Q scaled, fp16-pair words [t][kslot(h/2)], hi/lo split
__device__ uint32_t g_qlo[Bn * Tn * 32];
__device__ uint32_t g_kf[Bn * Tn * 32];    // K single-rounded fp16 words [t][kslot(h/2)]
__device__ unsigned short g_vfT[Bn * Hn * Tn];  // V^T single-rounded fp16 [b][h][eperm(t)]
__device__ uint32_t g_wf[3 * 32 * 64 * 16];     // W single-rounded words [which][kt][n][kslot(k/2)]

// ---------------- helpers ----------------
__device__ __forceinline__ unsigned short f16(float x) {
    unsigned short h;
    asm("cvt.rn.f16.f32 %0, %1;" : "=h"(h) : "f"(x));
    return h;
}
__device__ __forceinline__ float ff16(unsigned short h) {
    float f;
    asm("cvt.f32.f16 %0, %1;" : "=f"(f) : "h"(h));
    return f;
}
__device__ __forceinline__ uint32_t pkb(unsigned short lo, unsigned short hi) {
    uint32_t r;
    asm("mov.b32 %0, {%1, %2};" : "=r"(r) : "h"(lo), "h"(hi));
    return r;
}
// split pair (x0 = k-even, x1 = k-odd) into fp16 hi-word and lo-word
__device__ __forceinline__ void sph2(float x0, float x1, uint32_t& hw, uint32_t& lw) {
    unsigned short h0 = f16(x0), h1 = f16(x1);
    unsigned short l0 = f16(x0 - ff16(h0)), l1 = f16(x1 - ff16(h1));
    hw = pkb(h0, h1);
    lw = pkb(l0, l1);
}
// single-round pair to one fp16 word
__device__ __forceinline__ uint32_t rph2(float x0, float x1) {
    return pkb(f16(x0), f16(x1));
}
// fp16 m16n8k16 mma, fp32 accum
__device__ __forceinline__ void mmah(float c[4],
                                     uint32_t a0, uint32_t a1, uint32_t a2, uint32_t a3,
                                     uint32_t b0, uint32_t b1) {
    asm volatile(
        "mma.sync.aligned.m16n8k16.row.col.f32.f16.f16.f32 "
        "{%0,%1,%2,%3}, {%4,%5,%6,%7}, {%8,%9}, {%0,%1,%2,%3};"
        : "+f"(c[0]), "+f"(c[1]), "+f"(c[2]), "+f"(c[3])
        : "r"(a0), "r"(a1), "r"(a2), "r"(a3), "r"(b0), "r"(b1));
}
// word interleave within 8-groups: (w, w+4) adjacent
__device__ __forceinline__ int kslot(int w) {
    return (w & ~7) + 2 * (w & 3) + ((w >> 2) & 1);
}
// element permutation for V^T rows so contiguous copy yields kslot word order
__device__ __forceinline__ int eperm(int t) {
    int w = (t >> 1) & 7;
    int sl = 2 * (w & 3) + ((w >> 2) & 1);
    return (t & ~15) + sl * 2 + (t & 1);
}
__device__ __forceinline__ uint32_t smem_u32(const void* p) {
    uint32_t a;
    asm("{ .reg .u64 t; cvta.to.shared.u64 t, %1; cvt.u32.u64 %0, t; }" : "=r"(a) : "l"(p));
    return a;
}
#define CP16(dst, src) \
    asm volatile("cp.async.cg.shared.global [%0], [%1], 16;" :: "r"(dst), "l"(src))
#define CP_COMMIT() asm volatile("cp.async.commit_group;" ::: "memory")
#define CP_WAIT0()  asm volatile("cp.async.wait_group 0;" ::: "memory")
#define CP_WAIT1()  asm volatile("cp.async.wait_group 1;" ::: "memory")

// ================= Kernel 0: W -> single-rounded fp16 words =================
__global__ void wsplit_kernel(const float* __restrict__ wq,
                              const float* __restrict__ wk,
                              const float* __restrict__ wv) {
    const int which = blockIdx.y, kt = blockIdx.x;
    const float* w = (which == 0) ? wq : (which == 1) ? wk : wv;
    const int tid = threadIdx.x;
#pragma unroll
    for (int i = 0; i < 4; i++) {
        int e = tid + i * 256;        // 0..1023 words
        int n = e & 63, wp = e >> 6;  // wp 0..15
        float x0 = w[(size_t)(kt * 32 + 2 * wp) * Hn + n];
        float x1 = w[(size_t)(kt * 32 + 2 * wp + 1) * Hn + n];
        int dst = ((which * 32 + kt) * 64 + n) * 16 + kslot(wp);
        g_wf[dst] = rph2(x0, x1);
    }
}

// ================= Kernel 1: QKV projection (2-stage pipeline, fp16 1-term) =================
// grid (256, 3), block 128 (4 warps, m32 x n64). M_TILE=128, K chunks of 32.
// A = x single-rounded fp16 (in regs from SMEM fp32); B = W single-rounded (precomputed).
// Dynamic SMEM: 2 stages x (As 20480B + Bf 6144B) = 53248 B -> 4 CTAs/SM.
#define QSTG_B 26624
#define QBF_OFF 20480
__global__ __launch_bounds__(128) void qkv_kernel(const float* __restrict__ x)
{
    extern __shared__ __align__(16) uint32_t qdsm[];

    const int which = blockIdx.y;
    const int m0 = blockIdx.x * 128;
    const int tid = threadIdx.x;
    const int wid = tid >> 5, lane = tid & 31;
    const int lr = lane >> 2, lc = lane & 3;

    const uint32_t dsmA = smem_u32(qdsm);

    float acc[2][8][4];
#pragma unroll
    for (int mt = 0; mt < 2; mt++)
#pragma unroll
        for (int nt = 0; nt < 8; nt++)
#pragma unroll
            for (int i = 0; i < 4; i++) acc[mt][nt][i] = 0.f;

#define FILL_QKV(stage, ktv)                                                         \
    {                                                                                \
        uint32_t sb = dsmA + (stage) * QSTG_B;                                       \
        _Pragma("unroll")                                                            \
        for (int l = 0; l < 8; l++) {                                                \
            int idx = tid + l * 128;                                                 \
            int row = idx >> 3, ch = idx & 7;                                        \
            CP16(sb + row * 160 + ch * 16,                                           \
                 x + (size_t)(m0 + row) * Cn + (ktv) * 32 + ch * 4);                 \
        }                                                                            \
        const size_t tb = (size_t)(which * 32 + (ktv)) * 1024;                       \
        _Pragma("unroll")                                                            \
        for (int l = 0; l < 2; l++) {                                                \
            int idx = tid + l * 128;          /* 0..255 */                           \
            int n = idx >> 2, ch = idx & 3;                                          \
            CP16(sb + QBF_OFF + n * 96 + ch * 16,                                    \
                 g_wf + tb + n * 16 + ch * 4);                                       \
        }                                                                            \
        CP_COMMIT();                                                                 \
    }

    FILL_QKV(0, 0);

    for (int kt = 0; kt < Cn / 32; kt++) {
        const int buf = kt & 1;
        const float* As = (const float*)(qdsm + buf * (QSTG_B / 4));
        const uint32_t* Bf = qdsm + buf * (QSTG_B / 4) + QBF_OFF / 4;

        if (kt + 1 < Cn / 32) {
            FILL_QKV(buf ^ 1, kt + 1);
            CP_WAIT1();
        } else {
            CP_WAIT0();
        }
        __syncthreads();

#pragma unroll
        for (int c = 0; c < 2; c++) {         // two k16 chunks
            uint32_t af[2][4];
#pragma unroll
            for (int mt = 0; mt < 2; mt++) {
                int rb = wid * 32 + mt * 16 + lr;
                float2 p0 = *(const float2*)&As[rb * 40 + c * 16 + 2 * lc];
                float2 p1 = *(const float2*)&As[(rb + 8) * 40 + c * 16 + 2 * lc];
                float2 p2 = *(const float2*)&As[rb * 40 + c * 16 + 8 + 2 * lc];
                float2 p3 = *(const float2*)&As[(rb + 8) * 40 + c * 16 + 8 + 2 * lc];
                af[mt][0] = rph2(p0.x, p0.y);
                af[mt][1] = rph2(p1.x, p1.y);
                af[mt][2] = rph2(p2.x, p2.y);
                af[mt][3] = rph2(p3.x, p3.y);
            }
#pragma unroll
            for (int nt = 0; nt < 8; nt++) {
                uint2 bf = *(const uint2*)&Bf[(nt * 8 + lr) * 24 + c * 8 + 2 * lc];
#pragma unroll
                for (int mt = 0; mt < 2; mt++)
                    mmah(acc[mt][nt], af[mt][0], af[mt][1], af[mt][2], af[mt][3], bf.x, bf.y);
            }
        }
        __syncthreads();  // stage reads done before it is refilled
    }

    // Epilogue: pack by output kind
#pragma unroll
    for (int mt = 0; mt < 2; mt++)
#pragma unroll
        for (int rr = 0; rr < 2; rr++) {
            int row = m0 + wid * 32 + mt * 16 + rr * 8 + lr;
#pragma unroll
            for (int nt = 0; nt < 8; nt++) {
                float v0 = acc[mt][nt][rr * 2 + 0];
                float v1 = acc[mt][nt][rr * 2 + 1];
                int col0 = nt * 8 + 2 * lc;
                int sl = kslot(nt * 4 + lc);
                if (which == 0) {
                    uint32_t hw, lw;
                    sph2(v0 * 0.125f, v1 * 0.125f, hw, lw);
                    g_qhi[(size_t)row * 32 + sl] = hw;
                    g_qlo[(size_t)row * 32 + sl] = lw;
                } else if (which == 1) {
                    g_kf[(size_t)row * 32 + sl] = rph2(v0, v1);
                } else {
                    int bb = row >> 11, t = row & 2047;
                    int ep = eperm(t);
                    g_vfT[(size_t)(bb * Hn + col0) * Tn + ep] = f16(v0);
                    g_vfT[(size_t)(bb * Hn + col0 + 1) * Tn + ep] = f16(v1);
                }
            }
        }
}

// ================= Kernel 2: flash attention (register P, fp16 2-term, 2-stage K/V) =================
// grid 256 (heavy-first), block 256 (8 warps, each m16 x n64). Q_TILE=128, KV_TILE=64.
// Static SMEM: 2 stages x (Kf 2560 + Vf 2560) words = 40960 B. (Unchanged from R13.)
#define STG_W 5120    // words per stage
#define ARR_W 2560    // words per array (64 * 40)
__global__ __launch_bounds__(256) void attn_kernel(float* __restrict__ out)
{
    __shared__ __align__(16) uint32_t dsm[2 * STG_W];

    const int qt = 15 - (blockIdx.x >> 4);
    const int b  = blockIdx.x & 15;
    const int q0 = qt * 128;
    const size_t bT = (size_t)b * Tn;
    const int tid = threadIdx.x;
    const int wid = tid >> 5, lane = tid & 31;
    const int lr = lane >> 2, lc = lane & 3;
    const int r0l = wid * 16 + lr, r1l = r0l + 8;    // local q rows (0..127)

    const uint32_t dsmA = smem_u32(dsm);
    const int arr = wid >> 2, quarter = wid & 3;     // fill ownership: 2 arrays x 4 quarters

    // Q fragments: pre-split fp16 words straight from global
    uint32_t qah[4][4], qal[4][4];
#pragma unroll
    for (int c = 0; c < 4; c++) {
        uint2 h0 = *(const uint2*)&g_qhi[(bT + q0 + r0l) * 32 + c * 8 + 2 * lc];
        uint2 h1 = *(const uint2*)&g_qhi[(bT + q0 + r1l) * 32 + c * 8 + 2 * lc];
        uint2 l0 = *(const uint2*)&g_qlo[(bT + q0 + r0l) * 32 + c * 8 + 2 * lc];
        uint2 l1 = *(const uint2*)&g_qlo[(bT + q0 + r1l) * 32 + c * 8 + 2 * lc];
        qah[c][0] = h0.x; qah[c][1] = h1.x; qah[c][2] = h0.y; qah[c][3] = h1.y;
        qal[c][0] = l0.x; qal[c][1] = l1.x; qal[c][2] = l0.y; qal[c][3] = l1.y;
    }

    float o[8][4];
    float mrow[2] = { -1e30f, -1e30f };
    float lrow[2] = { 0.f, 0.f };
#pragma unroll
    for (int nt = 0; nt < 8; nt++)
#pragma unroll
        for (int i = 0; i < 4; i++) o[nt][i] = 0.f;

    const int n_iter = 2 * qt + 2;

    // fill: warp -> array arr, rows quarter*16..+15; 16 rows x 8 chunks = 128 chunks per warp
#define FILL_TILE(stage, s0v)                                                        \
    {                                                                                \
        uint32_t base = dsmA + ((stage) * STG_W + arr * ARR_W) * 4;                  \
        _Pragma("unroll")                                                            \
        for (int i = 0; i < 4; i++) {                                                \
            int c = lane + i * 32;                                                   \
            int row = quarter * 16 + (c >> 3), ch = c & 7;                           \
            if (arr == 0)                                                            \
                CP16(base + row * 160 + ch * 16,                                     \
                     g_kf + (bT + (s0v) + row) * 32 + ch * 4);                       \
            else                                                                     \
                CP16(base + row * 160 + ch * 16,                                     \
                     g_vfT + (size_t)(b * Hn + row) * Tn + (s0v) + ch * 8);          \
        }                                                                            \
        CP_COMMIT();                                                                 \
    }

    FILL_TILE(0, 0);   // prefetch tile 0

    for (int st = 0; st < n_iter; st++) {
        const int s0 = st * 64;
        const int buf = st & 1;
        const uint32_t* Kf = dsm + buf * STG_W;
        const uint32_t* Vf = Kf + ARR_W;

        if (st + 1 < n_iter) {
            FILL_TILE(buf ^ 1, s0 + 64);
            CP_WAIT1();
        } else {
            CP_WAIT0();
        }
        __syncthreads();

        // ---- S = Q K^T (2 terms) ----
        float sacc[8][4];
#pragma unroll
        for (int nt = 0; nt < 8; nt++)
#pragma unroll
            for (int i = 0; i < 4; i++) sacc[nt][i] = 0.f;

#pragma unroll
        for (int c = 0; c < 4; c++) {
#pragma unroll
            for (int nt = 0; nt < 8; nt++) {
                uint2 bf = *(const uint2*)&Kf[(nt * 8 + lr) * 40 + c * 8 + 2 * lc];
                mmah(sacc[nt], qah[c][0], qah[c][1], qah[c][2], qah[c][3], bf.x, bf.y);
                mmah(sacc[nt], qal[c][0], qal[c][1], qal[c][2], qal[c][3], bf.x, bf.y);
            }
        }

        // ---- causal mask (tiles overlapping the diagonal) ----
        if (st >= 2 * qt) {
            int r0g = q0 + r0l, r1g = q0 + r1l;
#pragma unroll
            for (int nt = 0; nt < 8; nt++) {
                int cg = s0 + nt * 8 + 2 * lc;
                if (cg > r0g)     sacc[nt][0] = -1e30f;
                if (cg + 1 > r0g) sacc[nt][1] = -1e30f;
                if (cg > r1g)     sacc[nt][2] = -1e30f;
                if (cg + 1 > r1g) sacc[nt][3] = -1e30f;
            }
        }

        // ---- online softmax ----
        float mx0 = -1e30f, mx1 = -1e30f;
#pragma unroll
        for (int nt = 0; nt < 8; nt++) {
            mx0 = fmaxf(mx0, fmaxf(sacc[nt][0], sacc[nt][1]));
            mx1 = fmaxf(mx1, fmaxf(sacc[nt][2], sacc[nt][3]));
        }
        mx0 = fmaxf(mx0, __shfl_xor_sync(0xffffffffu, mx0, 1));
        mx0 = fmaxf(mx0, __shfl_xor_sync(0xffffffffu, mx0, 2));
        mx1 = fmaxf(mx1, __shfl_xor_sync(0xffffffffu, mx1, 1));
        mx1 = fmaxf(mx1, __shfl_xor_sync(0xffffffffu, mx1, 2));

        float mn0 = fmaxf(mrow[0], mx0), mn1 = fmaxf(mrow[1], mx1);
        float f0 = __expf(mrow[0] - mn0), f1 = __expf(mrow[1] - mn1);
        mrow[0] = mn0; mrow[1] = mn1;

        float sum0 = 0.f, sum1 = 0.f;
#pragma unroll
        for (int nt = 0; nt < 8; nt++) {
            sacc[nt][0] = __expf(sacc[nt][0] - mn0);
            sacc[nt][1] = __expf(sacc[nt][1] - mn0);
            sacc[nt][2] = __expf(sacc[nt][2] - mn1);
            sacc[nt][3] = __expf(sacc[nt][3] - mn1);
            sum0 += sacc[nt][0] + sacc[nt][1];
            sum1 += sacc[nt][2] + sacc[nt][3];
        }
        sum0 += __shfl_xor_sync(0xffffffffu, sum0, 1);
        sum0 += __shfl_xor_sync(0xffffffffu, sum0, 2);
        sum1 += __shfl_xor_sync(0xffffffffu, sum1, 1);
        sum1 += __shfl_xor_sync(0xffffffffu, sum1, 2);
        lrow[0] = lrow[0] * f0 + sum0;
        lrow[1] = lrow[1] * f1 + sum1;

#pragma unroll
        for (int nt = 0; nt < 8; nt++) {
            o[nt][0] *= f0; o[nt][1] *= f0;
            o[nt][2] *= f1; o[nt][3] *= f1;
        }

        // ---- O += P V, P split fp16 hi/lo in registers (FA2 layout identity) ----
#pragma unroll
        for (int c = 0; c < 4; c++) {
            uint32_t ph[4], pl[4];
            sph2(sacc[2 * c][0],     sacc[2 * c][1],     ph[0], pl[0]);
            sph2(sacc[2 * c][2],     sacc[2 * c][3],     ph[1], pl[1]);
            sph2(sacc[2 * c + 1][0], sacc[2 * c + 1][1], ph[2], pl[2]);
            sph2(sacc[2 * c + 1][2], sacc[2 * c + 1][3], ph[3], pl[3]);
#pragma unroll
            for (int nt = 0; nt < 8; nt++) {
                uint2 vf = *(const uint2*)&Vf[(nt * 8 + lr) * 40 + c * 8 + 2 * lc];
                mmah(o[nt], ph[0], ph[1], ph[2], ph[3], vf.x, vf.y);
                mmah(o[nt], pl[0], pl[1], pl[2], pl[3], vf.x, vf.y);
            }
        }

        __syncthreads();  // all reads of this stage done before it is refilled
    }

    float inv0 = 1.0f / lrow[0], inv1 = 1.0f / lrow[1];
#pragma unroll
    for (int nt = 0; nt < 8; nt++) {
        int col = nt * 8 + 2 * lc;
        *(float2*)&out[(bT + q0 + r0l) * Hn + col] =
            make_float2(o[nt][0] * inv0, o[nt][1] * inv0);
        *(float2*)&out[(bT + q0 + r1l) * Hn + col] =
            make_float2(o[nt][2] * inv1, o[nt][3] * inv1);
    }
}

// ================= launch =================
extern "C" void kernel_launch(void* const* d_in, const int* in_sizes, int n_in,
                              void* d_out, int out_size)
{
    const float* x  = (const float*)d_in[0];
    const float* wq = (const float*)d_in[1];
    const float* wk = (const float*)d_in[2];
    const float* wv = (const float*)d_in[3];
    float* out = (float*)d_out;

    wsplit_kernel<<<dim3(32, 3), 256>>>(wq, wk, wv);

    const int qkv_smem = 2 * QSTG_B;  // 53248 B
    cudaFuncSetAttribute(qkv_kernel, cudaFuncAttributeMaxDynamicSharedMemorySize, qkv_smem);
    qkv_kernel<<<dim3((Bn * Tn) / 128, 3), 128, qkv_smem>>>(x);

    attn_kernel<<<256, 256>>>(out);
}

// round 15
// speedup vs baseline: 3.9916x; 1.2186x over previous
#include <cuda_runtime.h>
#include <cstdint>

#define Bn 16
#define Tn 2048
#define Cn 1024
#define Hn 64

// ---------------- global scratch (fp16 operands) ----------------
__device__ uint32_t g_qf[Bn * Tn * 32];    // Q scaled, single-rounded fp16 words [t][kslot(h/2)]
__device__ uint32_t g_kf[Bn * Tn * 32];    // K single-rounded fp16 words [t][kslot(h/2)]
__device__ unsigned short g_vfT[Bn * Hn * Tn];  // V^T single-rounded fp16 [b][h][eperm(t)]
__device__ uint32_t g_wf[3 * 32 * 64 * 16];     // W single-rounded words [which][kt][n][kslot(k/2)]

// ---------------- helpers ----------------
__device__ __forceinline__ unsigned short f16(float x) {
    unsigned short h;
    asm("cvt.rn.f16.f32 %0, %1;" : "=h"(h) : "f"(x));
    return h;
}
__device__ __forceinline__ uint32_t pkb(unsigned short lo, unsigned short hi) {
    uint32_t r;
    asm("mov.b32 %0, {%1, %2};" : "=r"(r) : "h"(lo), "h"(hi));
    return r;
}
// single-round pair to one fp16 word
__device__ __forceinline__ uint32_t rph2(float x0, float x1) {
    return pkb(f16(x0), f16(x1));
}
// fp16 m16n8k16 mma, fp32 accum
__device__ __forceinline__ void mmah(float c[4],
                                     uint32_t a0, uint32_t a1, uint32_t a2, uint32_t a3,
                                     uint32_t b0, uint32_t b1) {
    asm volatile(
        "mma.sync.aligned.m16n8k16.row.col.f32.f16.f16.f32 "
        "{%0,%1,%2,%3}, {%4,%5,%6,%7}, {%8,%9}, {%0,%1,%2,%3};"
        : "+f"(c[0]), "+f"(c[1]), "+f"(c[2]), "+f"(c[3])
        : "r"(a0), "r"(a1), "r"(a2), "r"(a3), "r"(b0), "r"(b1));
}
// word interleave within 8-groups: (w, w+4) adjacent
__device__ __forceinline__ int kslot(int w) {
    return (w & ~7) + 2 * (w & 3) + ((w >> 2) & 1);
}
// element permutation for V^T rows so contiguous copy yields kslot word order
__device__ __forceinline__ int eperm(int t) {
    int w = (t >> 1) & 7;
    int sl = 2 * (w & 3) + ((w >> 2) & 1);
    return (t & ~15) + sl * 2 + (t & 1);
}
__device__ __forceinline__ uint32_t smem_u32(const void* p) {
    uint32_t a;
    asm("{ .reg .u64 t; cvta.to.shared.u64 t, %1; cvt.u32.u64 %0, t; }" : "=r"(a) : "l"(p));
    return a;
}
#define CP16(dst, src) \
    asm volatile("cp.async.cg.shared.global [%0], [%1], 16;" :: "r"(dst), "l"(src))
#define CP_COMMIT() asm volatile("cp.async.commit_group;" ::: "memory")
#define CP_WAIT0()  asm volatile("cp.async.wait_group 0;" ::: "memory")
#define CP_WAIT1()  asm volatile("cp.async.wait_group 1;" ::: "memory")

// ================= Kernel 0: W -> single-rounded fp16 words =================
__global__ void wsplit_kernel(const float* __restrict__ wq,
                              const float* __restrict__ wk,
                              const float* __restrict__ wv) {
    const int which = blockIdx.y, kt = blockIdx.x;
    const float* w = (which == 0) ? wq : (which == 1) ? wk : wv;
    const int tid = threadIdx.x;
#pragma unroll
    for (int i = 0; i < 4; i++) {
        int e = tid + i * 256;        // 0..1023 words
        int n = e & 63, wp = e >> 6;  // wp 0..15
        float x0 = w[(size_t)(kt * 32 + 2 * wp) * Hn + n];
        float x1 = w[(size_t)(kt * 32 + 2 * wp + 1) * Hn + n];
        int dst = ((which * 32 + kt) * 64 + n) * 16 + kslot(wp);
        g_wf[dst] = rph2(x0, x1);
    }
}

// ================= Kernel 1: QKV projection (2-stage pipeline, fp16 1-term) =================
// grid (256, 3), block 128 (4 warps, m32 x n64). M_TILE=128, K chunks of 32.
// Dynamic SMEM: 2 stages x (As 20480B + Bf 6144B) = 53248 B -> 4 CTAs/SM.
#define QSTG_B 26624
#define QBF_OFF 20480
__global__ __launch_bounds__(128) void qkv_kernel(const float* __restrict__ x)
{
    extern __shared__ __align__(16) uint32_t qdsm[];

    const int which = blockIdx.y;
    const int m0 = blockIdx.x * 128;
    const int tid = threadIdx.x;
    const int wid = tid >> 5, lane = tid & 31;
    const int lr = lane >> 2, lc = lane & 3;

    const uint32_t dsmA = smem_u32(qdsm);

    float acc[2][8][4];
#pragma unroll
    for (int mt = 0; mt < 2; mt++)
#pragma unroll
        for (int nt = 0; nt < 8; nt++)
#pragma unroll
            for (int i = 0; i < 4; i++) acc[mt][nt][i] = 0.f;

#define FILL_QKV(stage, ktv)                                                         \
    {                                                                                \
        uint32_t sb = dsmA + (stage) * QSTG_B;                                       \
        _Pragma("unroll")                                                            \
        for (int l = 0; l < 8; l++) {                                                \
            int idx = tid + l * 128;                                                 \
            int row = idx >> 3, ch = idx & 7;                                        \
            CP16(sb + row * 160 + ch * 16,                                           \
                 x + (size_t)(m0 + row) * Cn + (ktv) * 32 + ch * 4);                 \
        }                                                                            \
        const size_t tb = (size_t)(which * 32 + (ktv)) * 1024;                       \
        _Pragma("unroll")                                                            \
        for (int l = 0; l < 2; l++) {                                                \
            int idx = tid + l * 128;          /* 0..255 */                           \
            int n = idx >> 2, ch = idx & 3;                                          \
            CP16(sb + QBF_OFF + n * 96 + ch * 16,                                    \
                 g_wf + tb + n * 16 + ch * 4);                                       \
        }                                                                            \
        CP_COMMIT();                                                                 \
    }

    FILL_QKV(0, 0);

    for (int kt = 0; kt < Cn / 32; kt++) {
        const int buf = kt & 1;
        const float* As = (const float*)(qdsm + buf * (QSTG_B / 4));
        const uint32_t* Bf = qdsm + buf * (QSTG_B / 4) + QBF_OFF / 4;

        if (kt + 1 < Cn / 32) {
            FILL_QKV(buf ^ 1, kt + 1);
            CP_WAIT1();
        } else {
            CP_WAIT0();
        }
        __syncthreads();

#pragma unroll
        for (int c = 0; c < 2; c++) {         // two k16 chunks
            uint32_t af[2][4];
#pragma unroll
            for (int mt = 0; mt < 2; mt++) {
                int rb = wid * 32 + mt * 16 + lr;
                float2 p0 = *(const float2*)&As[rb * 40 + c * 16 + 2 * lc];
                float2 p1 = *(const float2*)&As[(rb + 8) * 40 + c * 16 + 2 * lc];
                float2 p2 = *(const float2*)&As[rb * 40 + c * 16 + 8 + 2 * lc];
                float2 p3 = *(const float2*)&As[(rb + 8) * 40 + c * 16 + 8 + 2 * lc];
                af[mt][0] = rph2(p0.x, p0.y);
                af[mt][1] = rph2(p1.x, p1.y);
                af[mt][2] = rph2(p2.x, p2.y);
                af[mt][3] = rph2(p3.x, p3.y);
            }
#pragma unroll
            for (int nt = 0; nt < 8; nt++) {
                uint2 bf = *(const uint2*)&Bf[(nt * 8 + lr) * 24 + c * 8 + 2 * lc];
#pragma unroll
                for (int mt = 0; mt < 2; mt++)
                    mmah(acc[mt][nt], af[mt][0], af[mt][1], af[mt][2], af[mt][3], bf.x, bf.y);
            }
        }
        __syncthreads();  // stage reads done before it is refilled
    }

    // Epilogue: pack by output kind
#pragma unroll
    for (int mt = 0; mt < 2; mt++)
#pragma unroll
        for (int rr = 0; rr < 2; rr++) {
            int row = m0 + wid * 32 + mt * 16 + rr * 8 + lr;
#pragma unroll
            for (int nt = 0; nt < 8; nt++) {
                float v0 = acc[mt][nt][rr * 2 + 0];
                float v1 = acc[mt][nt][rr * 2 + 1];
                int col0 = nt * 8 + 2 * lc;
                int sl = kslot(nt * 4 + lc);
                if (which == 0) {
                    g_qf[(size_t)row * 32 + sl] = rph2(v0 * 0.125f, v1 * 0.125f);
                } else if (which == 1) {
                    g_kf[(size_t)row * 32 + sl] = rph2(v0, v1);
                } else {
                    int bb = row >> 11, t = row & 2047;
                    int ep = eperm(t);
                    g_vfT[(size_t)(bb * Hn + col0) * Tn + ep] = f16(v0);
                    g_vfT[(size_t)(bb * Hn + col0 + 1) * Tn + ep] = f16(v1);
                }
            }
        }
}

// ================= Kernel 2: flash attention (fp16 1-term S and PV, 2-stage K/V) =================
// grid 256 (heavy-first), block 256 (8 warps, each m16 x n64). Q_TILE=128, KV_TILE=64.
// Static SMEM: 2 stages x (Kf 2560 + Vf 2560) words = 40960 B.
#define STG_W 5120    // words per stage
#define ARR_W 2560    // words per array (64 * 40)
__global__ __launch_bounds__(256) void attn_kernel(float* __restrict__ out)
{
    __shared__ __align__(16) uint32_t dsm[2 * STG_W];

    const int qt = 15 - (blockIdx.x >> 4);
    const int b  = blockIdx.x & 15;
    const int q0 = qt * 128;
    const size_t bT = (size_t)b * Tn;
    const int tid = threadIdx.x;
    const int wid = tid >> 5, lane = tid & 31;
    const int lr = lane >> 2, lc = lane & 3;
    const int r0l = wid * 16 + lr, r1l = r0l + 8;    // local q rows (0..127)

    const uint32_t dsmA = smem_u32(dsm);
    const int arr = wid >> 2, quarter = wid & 3;     // fill ownership: 2 arrays x 4 quarters

    // Q fragments: single-rounded fp16 words straight from global
    uint32_t qaf[4][4];
#pragma unroll
    for (int c = 0; c < 4; c++) {
        uint2 h0 = *(const uint2*)&g_qf[(bT + q0 + r0l) * 32 + c * 8 + 2 * lc];
        uint2 h1 = *(const uint2*)&g_qf[(bT + q0 + r1l) * 32 + c * 8 + 2 * lc];
        qaf[c][0] = h0.x; qaf[c][1] = h1.x; qaf[c][2] = h0.y; qaf[c][3] = h1.y;
    }

    float o[8][4];
    float mrow[2] = { -1e30f, -1e30f };
    float lrow[2] = { 0.f, 0.f };
#pragma unroll
    for (int nt = 0; nt < 8; nt++)
#pragma unroll
        for (int i = 0; i < 4; i++) o[nt][i] = 0.f;

    const int n_iter = 2 * qt + 2;

    // fill: warp -> array arr, rows quarter*16..+15; 16 rows x 8 chunks = 128 chunks per warp
#define FILL_TILE(stage, s0v)                                                        \
    {                                                                                \
        uint32_t base = dsmA + ((stage) * STG_W + arr * ARR_W) * 4;                  \
        _Pragma("unroll")                                                            \
        for (int i = 0; i < 4; i++) {                                                \
            int c = lane + i * 32;                                                   \
            int row = quarter * 16 + (c >> 3), ch = c & 7;                           \
            if (arr == 0)                                                            \
                CP16(base + row * 160 + ch * 16,                                     \
                     g_kf + (bT + (s0v) + row) * 32 + ch * 4);                       \
            else                                                                     \
                CP16(base + row * 160 + ch * 16,                                     \
                     g_vfT + (size_t)(b * Hn + row) * Tn + (s0v) + ch * 8);          \
        }                                                                            \
        CP_COMMIT();                                                                 \
    }

    FILL_TILE(0, 0);   // prefetch tile 0

    for (int st = 0; st < n_iter; st++) {
        const int s0 = st * 64;
        const int buf = st & 1;
        const uint32_t* Kf = dsm + buf * STG_W;
        const uint32_t* Vf = Kf + ARR_W;

        if (st + 1 < n_iter) {
            FILL_TILE(buf ^ 1, s0 + 64);
            CP_WAIT1();
        } else {
            CP_WAIT0();
        }
        __syncthreads();

        // ---- S = Q K^T (1 term) ----
        float sacc[8][4];
#pragma unroll
        for (int nt = 0; nt < 8; nt++)
#pragma unroll
            for (int i = 0; i < 4; i++) sacc[nt][i] = 0.f;

#pragma unroll
        for (int c = 0; c < 4; c++) {
#pragma unroll
            for (int nt = 0; nt < 8; nt++) {
                uint2 bf = *(const uint2*)&Kf[(nt * 8 + lr) * 40 + c * 8 + 2 * lc];
                mmah(sacc[nt], qaf[c][0], qaf[c][1], qaf[c][2], qaf[c][3], bf.x, bf.y);
            }
        }

        // ---- causal mask (tiles overlapping the diagonal) ----
        if (st >= 2 * qt) {
            int r0g = q0 + r0l, r1g = q0 + r1l;
#pragma unroll
            for (int nt = 0; nt < 8; nt++) {
                int cg = s0 + nt * 8 + 2 * lc;
                if (cg > r0g)     sacc[nt][0] = -1e30f;
                if (cg + 1 > r0g) sacc[nt][1] = -1e30f;
                if (cg > r1g)     sacc[nt][2] = -1e30f;
                if (cg + 1 > r1g) sacc[nt][3] = -1e30f;
            }
        }

        // ---- online softmax ----
        float mx0 = -1e30f, mx1 = -1e30f;
#pragma unroll
        for (int nt = 0; nt < 8; nt++) {
            mx0 = fmaxf(mx0, fmaxf(sacc[nt][0], sacc[nt][1]));
            mx1 = fmaxf(mx1, fmaxf(sacc[nt][2], sacc[nt][3]));
        }
        mx0 = fmaxf(mx0, __shfl_xor_sync(0xffffffffu, mx0, 1));
        mx0 = fmaxf(mx0, __shfl_xor_sync(0xffffffffu, mx0, 2));
        mx1 = fmaxf(mx1, __shfl_xor_sync(0xffffffffu, mx1, 1));
        mx1 = fmaxf(mx1, __shfl_xor_sync(0xffffffffu, mx1, 2));

        float mn0 = fmaxf(mrow[0], mx0), mn1 = fmaxf(mrow[1], mx1);
        float f0 = __expf(mrow[0] - mn0), f1 = __expf(mrow[1] - mn1);
        mrow[0] = mn0; mrow[1] = mn1;

        float sum0 = 0.f, sum1 = 0.f;
#pragma unroll
        for (int nt = 0; nt < 8; nt++) {
            sacc[nt][0] = __expf(sacc[nt][0] - mn0);
            sacc[nt][1] = __expf(sacc[nt][1] - mn0);
            sacc[nt][2] = __expf(sacc[nt][2] - mn1);
            sacc[nt][3] = __expf(sacc[nt][3] - mn1);
            sum0 += sacc[nt][0] + sacc[nt][1];
            sum1 += sacc[nt][2] + sacc[nt][3];
        }
        sum0 += __shfl_xor_sync(0xffffffffu, sum0, 1);
        sum0 += __shfl_xor_sync(0xffffffffu, sum0, 2);
        sum1 += __shfl_xor_sync(0xffffffffu, sum1, 1);
        sum1 += __shfl_xor_sync(0xffffffffu, sum1, 2);
        lrow[0] = lrow[0] * f0 + sum0;
        lrow[1] = lrow[1] * f1 + sum1;

#pragma unroll
        for (int nt = 0; nt < 8; nt++) {
            o[nt][0] *= f0; o[nt][1] *= f0;
            o[nt][2] *= f1; o[nt][3] *= f1;
        }

        // ---- O += P V, P single-rounded fp16 in registers (FA2 layout identity) ----
#pragma unroll
        for (int c = 0; c < 4; c++) {
            uint32_t pf[4];
            pf[0] = rph2(sacc[2 * c][0],     sacc[2 * c][1]);
            pf[1] = rph2(sacc[2 * c][2],     sacc[2 * c][3]);
            pf[2] = rph2(sacc[2 * c + 1][0], sacc[2 * c + 1][1]);
            pf[3] = rph2(sacc[2 * c + 1][2], sacc[2 * c + 1][3]);
#pragma unroll
            for (int nt = 0; nt < 8; nt++) {
                uint2 vf = *(const uint2*)&Vf[(nt * 8 + lr) * 40 + c * 8 + 2 * lc];
                mmah(o[nt], pf[0], pf[1], pf[2], pf[3], vf.x, vf.y);
            }
        }

        __syncthreads();  // all reads of this stage done before it is refilled
    }

    float inv0 = 1.0f / lrow[0], inv1 = 1.0f / lrow[1];
#pragma unroll
    for (int nt = 0; nt < 8; nt++) {
        int col = nt * 8 + 2 * lc;
        *(float2*)&out[(bT + q0 + r0l) * Hn + col] =
            make_float2(o[nt][0] * inv0, o[nt][1] * inv0);
        *(float2*)&out[(bT + q0 + r1l) * Hn + col] =
            make_float2(o[nt][2] * inv1, o[nt][3] * inv1);
    }
}

// ================= launch =================
extern "C" void kernel_launch(void* const* d_in, const int* in_sizes, int n_in,
                              void* d_out, int out_size)
{
    const float* x  = (const float*)d_in[0];
    const float* wq = (const float*)d_in[1];
    const float* wk = (const float*)d_in[2];
    const float* wv = (const float*)d_in[3];
    float* out = (float*)d_out;

    wsplit_kernel<<<dim3(32, 3), 256>>>(wq, wk, wv);

    const int qkv_smem = 2 * QSTG_B;  // 53248 B
    cudaFuncSetAttribute(qkv_kernel, cudaFuncAttributeMaxDynamicSharedMemorySize, qkv_smem);
    qkv_kernel<<<dim3((Bn * Tn) / 128, 3), 128, qkv_smem>>>(x);

    attn_kernel<<<256, 256>>>(out);
}

// round 16
// speedup vs baseline: 4.3454x; 1.0886x over previous
#include <cuda_runtime.h>
#include <cstdint>

#define Bn 16
#define Tn 2048
#define Cn 1024
#define Hn 64

// ---------------- global scratch (fp16 operands) ----------------
__device__ uint32_t g_qf[Bn * Tn * 32];    // Q scaled, single-rounded fp16 words [t][kslot(h/2)]
__device__ uint32_t g_kf[Bn * Tn * 32];    // K single-rounded fp16 words [t][kslot(h/2)]
__device__ unsigned short g_vfT[Bn * Hn * Tn];  // V^T single-rounded fp16 [b][h][eperm(t)]
__device__ uint32_t g_wf[3 * 32 * 64 * 16];     // W single-rounded words [which][kt][n][kslot(k/2)]

// ---------------- helpers ----------------
__device__ __forceinline__ unsigned short f16(float x) {
    unsigned short h;
    asm("cvt.rn.f16.f32 %0, %1;" : "=h"(h) : "f"(x));
    return h;
}
__device__ __forceinline__ uint32_t pkb(unsigned short lo, unsigned short hi) {
    uint32_t r;
    asm("mov.b32 %0, {%1, %2};" : "=r"(r) : "h"(lo), "h"(hi));
    return r;
}
// single-round pair to one fp16 word
__device__ __forceinline__ uint32_t rph2(float x0, float x1) {
    return pkb(f16(x0), f16(x1));
}
// fp16 m16n8k16 mma, fp32 accum
__device__ __forceinline__ void mmah(float c[4],
                                     uint32_t a0, uint32_t a1, uint32_t a2, uint32_t a3,
                                     uint32_t b0, uint32_t b1) {
    asm volatile(
        "mma.sync.aligned.m16n8k16.row.col.f32.f16.f16.f32 "
        "{%0,%1,%2,%3}, {%4,%5,%6,%7}, {%8,%9}, {%0,%1,%2,%3};"
        : "+f"(c[0]), "+f"(c[1]), "+f"(c[2]), "+f"(c[3])
        : "r"(a0), "r"(a1), "r"(a2), "r"(a3), "r"(b0), "r"(b1));
}
// word interleave within 8-groups: (w, w+4) adjacent
__device__ __forceinline__ int kslot(int w) {
    return (w & ~7) + 2 * (w & 3) + ((w >> 2) & 1);
}
// element permutation for V^T rows so contiguous copy yields kslot word order
__device__ __forceinline__ int eperm(int t) {
    int w = (t >> 1) & 7;
    int sl = 2 * (w & 3) + ((w >> 2) & 1);
    return (t & ~15) + sl * 2 + (t & 1);
}
__device__ __forceinline__ uint32_t smem_u32(const void* p) {
    uint32_t a;
    asm("{ .reg .u64 t; cvta.to.shared.u64 t, %1; cvt.u32.u64 %0, t; }" : "=r"(a) : "l"(p));
    return a;
}
#define CP16(dst, src) \
    asm volatile("cp.async.cg.shared.global [%0], [%1], 16;" :: "r"(dst), "l"(src))
#define CP_COMMIT() asm volatile("cp.async.commit_group;" ::: "memory")
#define CP_WAIT0()  asm volatile("cp.async.wait_group 0;" ::: "memory")
#define CP_WAIT1()  asm volatile("cp.async.wait_group 1;" ::: "memory")

// ================= Kernel 0: W -> single-rounded fp16 words =================
__global__ void wsplit_kernel(const float* __restrict__ wq,
                              const float* __restrict__ wk,
                              const float* __restrict__ wv) {
    const int which = blockIdx.y, kt = blockIdx.x;
    const float* w = (which == 0) ? wq : (which == 1) ? wk : wv;
    const int tid = threadIdx.x;
#pragma unroll
    for (int i = 0; i < 4; i++) {
        int e = tid + i * 256;        // 0..1023 words
        int n = e & 63, wp = e >> 6;  // wp 0..15
        float x0 = w[(size_t)(kt * 32 + 2 * wp) * Hn + n];
        float x1 = w[(size_t)(kt * 32 + 2 * wp + 1) * Hn + n];
        int dst = ((which * 32 + kt) * 64 + n) * 16 + kslot(wp);
        g_wf[dst] = rph2(x0, x1);
    }
}

// ================= Kernel 1: fused QKV projection (one x read for all 3 outputs) =================
// grid 256, block 256 (8 warps, each m16 x n64 x 3 outputs). M_TILE=128, K chunks of 32.
// Dynamic SMEM: 2 stages x (As 20480B + 3 x Bf 6144B) = 77824 B.
#define QSTG_B 38912
#define QB_OFF 20480          // byte offset of B tiles within stage (6144 B each)
__global__ __launch_bounds__(256) void qkv_kernel(const float* __restrict__ x)
{
    extern __shared__ __align__(16) uint32_t qdsm[];

    const int m0 = blockIdx.x * 128;
    const int tid = threadIdx.x;
    const int wid = tid >> 5, lane = tid & 31;
    const int lr = lane >> 2, lc = lane & 3;

    const uint32_t dsmA = smem_u32(qdsm);

    float acc[3][8][4];
#pragma unroll
    for (int wch = 0; wch < 3; wch++)
#pragma unroll
        for (int nt = 0; nt < 8; nt++)
#pragma unroll
            for (int i = 0; i < 4; i++) acc[wch][nt][i] = 0.f;

    // fill one K-chunk: A 1024 chunks + 3 B tiles 768 chunks, 256 threads -> 7/thread
#define FILL_QKV3(stage, ktv)                                                        \
    {                                                                                \
        uint32_t sb = dsmA + (stage) * QSTG_B;                                       \
        _Pragma("unroll")                                                            \
        for (int l = 0; l < 4; l++) {                                                \
            int idx = tid + l * 256;          /* 0..1023 */                          \
            int row = idx >> 3, ch = idx & 7;                                        \
            CP16(sb + row * 160 + ch * 16,                                           \
                 x + (size_t)(m0 + row) * Cn + (ktv) * 32 + ch * 4);                 \
        }                                                                            \
        _Pragma("unroll")                                                            \
        for (int l = 0; l < 3; l++) {                                                \
            int e = tid + l * 256;            /* 0..767 */                           \
            int wch = e >> 8;                                                        \
            int r = e & 255;                                                         \
            int n = r >> 2, ch = r & 3;                                              \
            CP16(sb + QB_OFF + wch * 6144 + n * 96 + ch * 16,                        \
                 g_wf + (size_t)((wch * 32 + (ktv)) * 64 + n) * 16 + ch * 4);        \
        }                                                                            \
        CP_COMMIT();                                                                 \
    }

    FILL_QKV3(0, 0);

    for (int kt = 0; kt < Cn / 32; kt++) {
        const int buf = kt & 1;
        const float* As = (const float*)(qdsm + buf * (QSTG_B / 4));
        const uint32_t* Bbase = qdsm + buf * (QSTG_B / 4) + QB_OFF / 4;

        if (kt + 1 < Cn / 32) {
            FILL_QKV3(buf ^ 1, kt + 1);
            CP_WAIT1();
        } else {
            CP_WAIT0();
        }
        __syncthreads();

#pragma unroll
        for (int c = 0; c < 2; c++) {         // two k16 chunks
            uint32_t af[4];
            {
                int rb = wid * 16 + lr;
                float2 p0 = *(const float2*)&As[rb * 40 + c * 16 + 2 * lc];
                float2 p1 = *(const float2*)&As[(rb + 8) * 40 + c * 16 + 2 * lc];
                float2 p2 = *(const float2*)&As[rb * 40 + c * 16 + 8 + 2 * lc];
                float2 p3 = *(const float2*)&As[(rb + 8) * 40 + c * 16 + 8 + 2 * lc];
                af[0] = rph2(p0.x, p0.y);
                af[1] = rph2(p1.x, p1.y);
                af[2] = rph2(p2.x, p2.y);
                af[3] = rph2(p3.x, p3.y);
            }
#pragma unroll
            for (int wch = 0; wch < 3; wch++) {
                const uint32_t* Bf = Bbase + wch * 1536;
#pragma unroll
                for (int nt = 0; nt < 8; nt++) {
                    uint2 bf = *(const uint2*)&Bf[(nt * 8 + lr) * 24 + c * 8 + 2 * lc];
                    mmah(acc[wch][nt], af[0], af[1], af[2], af[3], bf.x, bf.y);
                }
            }
        }
        __syncthreads();  // stage reads done before it is refilled
    }

    // Epilogue: pack by output kind. Warp owns rows r0 (c0/c1) and r0+8 (c2/c3).
    {
        int r0 = m0 + wid * 16 + lr;
#pragma unroll
        for (int rr = 0; rr < 2; rr++) {
            int row = r0 + rr * 8;
#pragma unroll
            for (int wch = 0; wch < 3; wch++)
#pragma unroll
                for (int nt = 0; nt < 8; nt++) {
                    float v0 = acc[wch][nt][rr * 2 + 0];
                    float v1 = acc[wch][nt][rr * 2 + 1];
                    int col0 = nt * 8 + 2 * lc;
                    int sl = kslot(nt * 4 + lc);
                    if (wch == 0) {
                        g_qf[(size_t)row * 32 + sl] = rph2(v0 * 0.125f, v1 * 0.125f);
                    } else if (wch == 1) {
                        g_kf[(size_t)row * 32 + sl] = rph2(v0, v1);
                    } else {
                        int bb = row >> 11, t = row & 2047;
                        int ep = eperm(t);
                        g_vfT[(size_t)(bb * Hn + col0) * Tn + ep] = f16(v0);
                        g_vfT[(size_t)(bb * Hn + col0 + 1) * Tn + ep] = f16(v1);
                    }
                }
        }
    }
}

// ================= Kernel 2: flash attention (fp16 1-term S and PV, 2-stage K/V; R15) =================
// grid 256 (heavy-first), block 256 (8 warps, each m16 x n64). Q_TILE=128, KV_TILE=64.
// Static SMEM: 2 stages x (Kf 2560 + Vf 2560) words = 40960 B.
#define STG_W 5120    // words per stage
#define ARR_W 2560    // words per array (64 * 40)
__global__ __launch_bounds__(256) void attn_kernel(float* __restrict__ out)
{
    __shared__ __align__(16) uint32_t dsm[2 * STG_W];

    const int qt = 15 - (blockIdx.x >> 4);
    const int b  = blockIdx.x & 15;
    const int q0 = qt * 128;
    const size_t bT = (size_t)b * Tn;
    const int tid = threadIdx.x;
    const int wid = tid >> 5, lane = tid & 31;
    const int lr = lane >> 2, lc = lane & 3;
    const int r0l = wid * 16 + lr, r1l = r0l + 8;    // local q rows (0..127)

    const uint32_t dsmA = smem_u32(dsm);
    const int arr = wid >> 2, quarter = wid & 3;     // fill ownership: 2 arrays x 4 quarters

    // Q fragments: single-rounded fp16 words straight from global
    uint32_t qaf[4][4];
#pragma unroll
    for (int c = 0; c < 4; c++) {
        uint2 h0 = *(const uint2*)&g_qf[(bT + q0 + r0l) * 32 + c * 8 + 2 * lc];
        uint2 h1 = *(const uint2*)&g_qf[(bT + q0 + r1l) * 32 + c * 8 + 2 * lc];
        qaf[c][0] = h0.x; qaf[c][1] = h1.x; qaf[c][2] = h0.y; qaf[c][3] = h1.y;
    }

    float o[8][4];
    float mrow[2] = { -1e30f, -1e30f };
    float lrow[2] = { 0.f, 0.f };
#pragma unroll
    for (int nt = 0; nt < 8; nt++)
#pragma unroll
        for (int i = 0; i < 4; i++) o[nt][i] = 0.f;

    const int n_iter = 2 * qt + 2;

    // fill: warp -> array arr, rows quarter*16..+15; 16 rows x 8 chunks = 128 chunks per warp
#define FILL_TILE(stage, s0v)                                                        \
    {                                                                                \
        uint32_t base = dsmA + ((stage) * STG_W + arr * ARR_W) * 4;                  \
        _Pragma("unroll")                                                            \
        for (int i = 0; i < 4; i++) {                                                \
            int c = lane + i * 32;                                                   \
            int row = quarter * 16 + (c >> 3), ch = c & 7;                           \
            if (arr == 0)                                                            \
                CP16(base + row * 160 + ch * 16,                                     \
                     g_kf + (bT + (s0v) + row) * 32 + ch * 4);                       \
            else                                                                     \
                CP16(base + row * 160 + ch * 16,                                     \
                     g_vfT + (size_t)(b * Hn + row) * Tn + (s0v) + ch * 8);          \
        }                                                                            \
        CP_COMMIT();                                                                 \
    }

    FILL_TILE(0, 0);   // prefetch tile 0

    for (int st = 0; st < n_iter; st++) {
        const int s0 = st * 64;
        const int buf = st & 1;
        const uint32_t* Kf = dsm + buf * STG_W;
        const uint32_t* Vf = Kf + ARR_W;

        if (st + 1 < n_iter) {
            FILL_TILE(buf ^ 1, s0 + 64);
            CP_WAIT1();
        } else {
            CP_WAIT0();
        }
        __syncthreads();

        // ---- S = Q K^T (1 term) ----
        float sacc[8][4];
#pragma unroll
        for (int nt = 0; nt < 8; nt++)
#pragma unroll
            for (int i = 0; i < 4; i++) sacc[nt][i] = 0.f;

#pragma unroll
        for (int c = 0; c < 4; c++) {
#pragma unroll
            for (int nt = 0; nt < 8; nt++) {
                uint2 bf = *(const uint2*)&Kf[(nt * 8 + lr) * 40 + c * 8 + 2 * lc];
                mmah(sacc[nt], qaf[c][0], qaf[c][1], qaf[c][2], qaf[c][3], bf.x, bf.y);
            }
        }

        // ---- causal mask (tiles overlapping the diagonal) ----
        if (st >= 2 * qt) {
            int r0g = q0 + r0l, r1g = q0 + r1l;
#pragma unroll
            for (int nt = 0; nt < 8; nt++) {
                int cg = s0 + nt * 8 + 2 * lc;
                if (cg > r0g)     sacc[nt][0] = -1e30f;
                if (cg + 1 > r0g) sacc[nt][1] = -1e30f;
                if (cg > r1g)     sacc[nt][2] = -1e30f;
                if (cg + 1 > r1g) sacc[nt][3] = -1e30f;
            }
        }

        // ---- online softmax ----
        float mx0 = -1e30f, mx1 = -1e30f;
#pragma unroll
        for (int nt = 0; nt < 8; nt++) {
            mx0 = fmaxf(mx0, fmaxf(sacc[nt][0], sacc[nt][1]));
            mx1 = fmaxf(mx1, fmaxf(sacc[nt][2], sacc[nt][3]));
        }
        mx0 = fmaxf(mx0, __shfl_xor_sync(0xffffffffu, mx0, 1));
        mx0 = fmaxf(mx0, __shfl_xor_sync(0xffffffffu, mx0, 2));
        mx1 = fmaxf(mx1, __shfl_xor_sync(0xffffffffu, mx1, 1));
        mx1 = fmaxf(mx1, __shfl_xor_sync(0xffffffffu, mx1, 2));

        float mn0 = fmaxf(mrow[0], mx0), mn1 = fmaxf(mrow[1], mx1);
        float f0 = __expf(mrow[0] - mn0), f1 = __expf(mrow[1] - mn1);
        mrow[0] = mn0; mrow[1] = mn1;

        float sum0 = 0.f, sum1 = 0.f;
#pragma unroll
        for (int nt = 0; nt < 8; nt++) {
            sacc[nt][0] = __expf(sacc[nt][0] - mn0);
            sacc[nt][1] = __expf(sacc[nt][1] - mn0);
            sacc[nt][2] = __expf(sacc[nt][2] - mn1);
            sacc[nt][3] = __expf(sacc[nt][3] - mn1);
            sum0 += sacc[nt][0] + sacc[nt][1];
            sum1 += sacc[nt][2] + sacc[nt][3];
        }
        sum0 += __shfl_xor_sync(0xffffffffu, sum0, 1);
        sum0 += __shfl_xor_sync(0xffffffffu, sum0, 2);
        sum1 += __shfl_xor_sync(0xffffffffu, sum1, 1);
        sum1 += __shfl_xor_sync(0xffffffffu, sum1, 2);
        lrow[0] = lrow[0] * f0 + sum0;
        lrow[1] = lrow[1] * f1 + sum1;

#pragma unroll
        for (int nt = 0; nt < 8; nt++) {
            o[nt][0] *= f0; o[nt][1] *= f0;
            o[nt][2] *= f1; o[nt][3] *= f1;
        }

        // ---- O += P V, P single-rounded fp16 in registers (FA2 layout identity) ----
#pragma unroll
        for (int c = 0; c < 4; c++) {
            uint32_t pf[4];
            pf[0] = rph2(sacc[2 * c][0],     sacc[2 * c][1]);
            pf[1] = rph2(sacc[2 * c][2],     sacc[2 * c][3]);
            pf[2] = rph2(sacc[2 * c + 1][0], sacc[2 * c + 1][1]);
            pf[3] = rph2(sacc[2 * c + 1][2], sacc[2 * c + 1][3]);
#pragma unroll
            for (int nt = 0; nt < 8; nt++) {
                uint2 vf = *(const uint2*)&Vf[(nt * 8 + lr) * 40 + c * 8 + 2 * lc];
                mmah(o[nt], pf[0], pf[1], pf[2], pf[3], vf.x, vf.y);
            }
        }

        __syncthreads();  // all reads of this stage done before it is refilled
    }

    float inv0 = 1.0f / lrow[0], inv1 = 1.0f / lrow[1];
#pragma unroll
    for (int nt = 0; nt < 8; nt++) {
        int col = nt * 8 + 2 * lc;
        *(float2*)&out[(bT + q0 + r0l) * Hn + col] =
            make_float2(o[nt][0] * inv0, o[nt][1] * inv0);
        *(float2*)&out[(bT + q0 + r1l) * Hn + col] =
            make_float2(o[nt][2] * inv1, o[nt][3] * inv1);
    }
}

// ================= launch =================
extern "C" void kernel_launch(void* const* d_in, const int* in_sizes, int n_in,
                              void* d_out, int out_size)
{
    const float* x  = (const float*)d_in[0];
    const float* wq = (const float*)d_in[1];
    const float* wk = (const float*)d_in[2];
    const float* wv = (const float*)d_in[3];
    float* out = (float*)d_out;

    wsplit_kernel<<<dim3(32, 3), 256>>>(wq, wk, wv);

    const int qkv_smem = 2 * QSTG_B;  // 77824 B
    cudaFuncSetAttribute(qkv_kernel, cudaFuncAttributeMaxDynamicSharedMemorySize, qkv_smem);
    qkv_kernel<<<256, 256, qkv_smem>>>(x);

    attn_kernel<<<256, 256>>>(out);
}